// round 12
// baseline (speedup 1.0000x reference)
#include <cuda_runtime.h>
#include <cuda_fp16.h>
#include <math.h>
#include <stdint.h>

// ---------------------------------------------------------------------------
// MoE dispatch/combine via mma.sync HMMA (sm_100 target):
//   out[m] = sum_k w[m,k] * silu(x[m] @ W[e(m,k)] + b[e(m,k)])
// R12: routing lists split by top-k slot. Pass A (k=0) plain-stores every
// output row (no zero-init needed); pass B (k=1, stream-ordered after A)
// does race-free load+add+store. NO atomics, NO init pass, NO combine pass.
// GEMM mainloop = proven R10 loop, unchanged.
// ---------------------------------------------------------------------------

#define N_NODE   8192
#define N_EDGE   65536
#define N_ANGLE  131072
#define ND       128
#define NSYM     768
#define EINFO    320
#define ADIM     128
#define DO_NODE  128
#define DO_EDGE  192
#define DO_ANGLE 96

// per-(expert,k) list capacity = 2x binomial mean
#define CAPN2 2048
#define CAPE2 16384
#define CAPA2 32768

#define OUT_M1    ((size_t)0)
#define OUT_M2    ((size_t)N_NODE * ND)
#define OUT_EDGE  (OUT_M2 + (size_t)N_NODE * ND)
#define OUT_ANGLE (OUT_EDGE + (size_t)N_EDGE * DO_EDGE)

// ---------------- device scratch -------------------------------------------
__device__ int   g_cnt[48];                 // [which 0..2][expert 0..7][k 0..1]
__device__ __align__(16) int   g_rows_node [16 * CAPN2];
__device__ __align__(16) float g_w_node    [16 * CAPN2];
__device__ __align__(16) int   g_rows_edge [16 * CAPE2];
__device__ __align__(16) float g_w_edge    [16 * CAPE2];
__device__ __align__(16) int   g_rows_angle[16 * CAPA2];
__device__ __align__(16) float g_w_angle   [16 * CAPA2];

// transposed weights: [E][DOUT][DIN] fp16 (K-major rows)
__device__ __align__(16) __half g_w1t[(size_t)8 * DO_NODE  * ND];
__device__ __align__(16) __half g_w2t[(size_t)8 * DO_NODE  * NSYM];
__device__ __align__(16) __half g_wet[(size_t)8 * DO_EDGE  * EINFO];
__device__ __align__(16) __half g_wat[(size_t)8 * DO_ANGLE * ADIM];

// ---------------- helpers ---------------------------------------------------
__device__ __forceinline__ uint32_t smem_u32(const void* p) {
    uint32_t a;
    asm("{ .reg .u64 t; cvta.to.shared.u64 t, %1; cvt.u32.u64 %0, t; }"
        : "=r"(a) : "l"(p));
    return a;
}

__device__ __forceinline__ uint32_t h2b(__half2 h) {
    return *reinterpret_cast<uint32_t*>(&h);
}

#define LDMATRIX_X4(r0, r1, r2, r3, addr) \
    asm volatile("ldmatrix.sync.aligned.m8n8.x4.shared.b16 {%0,%1,%2,%3}, [%4];" \
                 : "=r"(r0), "=r"(r1), "=r"(r2), "=r"(r3) : "r"(addr))

#define LDMATRIX_X2(r0, r1, addr) \
    asm volatile("ldmatrix.sync.aligned.m8n8.x2.shared.b16 {%0,%1}, [%2];" \
                 : "=r"(r0), "=r"(r1) : "r"(addr))

#define MMA_16816(c, a, b) \
    asm volatile("mma.sync.aligned.m16n8k16.row.col.f32.f16.f16.f32 " \
                 "{%0,%1,%2,%3}, {%4,%5,%6,%7}, {%8,%9}, {%0,%1,%2,%3};" \
                 : "+f"((c)[0]), "+f"((c)[1]), "+f"((c)[2]), "+f"((c)[3]) \
                 : "r"((a)[0]), "r"((a)[1]), "r"((a)[2]), "r"((a)[3]), \
                   "r"((b)[0]), "r"((b)[1]))

#define STS128(addr, v0, v1, v2, v3) \
    asm volatile("st.shared.v4.b32 [%0], {%1,%2,%3,%4};" \
                 :: "r"(addr), "r"(v0), "r"(v1), "r"(v2), "r"(v3) : "memory")

// ---------------- init: zero counters ---------------------------------------
__global__ void init_kernel() {
    if (threadIdx.x < 48) g_cnt[threadIdx.x] = 0;
}

// ---------------- coalesced transpose+convert weights -----------------------
template<int WHICH>
__global__ void wcvt_kernel(const float* __restrict__ W) {
    constexpr int DIN  = (WHICH == 0) ? ND : (WHICH == 1) ? NSYM : (WHICH == 2) ? EINFO : ADIM;
    constexpr int DOUT = (WHICH <= 1) ? DO_NODE : (WHICH == 2) ? DO_EDGE : DO_ANGLE;
    __half* Wt;
    if      (WHICH == 0) Wt = g_w1t;
    else if (WHICH == 1) Wt = g_w2t;
    else if (WHICH == 2) Wt = g_wet;
    else                 Wt = g_wat;

    __shared__ float t[32][33];
    const int e  = blockIdx.y;
    const int nk = DIN / 32;
    const int k0 = (blockIdx.x % nk) * 32;
    const int n0 = (blockIdx.x / nk) * 32;
    const int tx = threadIdx.x, ty = threadIdx.y;
#pragma unroll
    for (int i = 0; i < 4; ++i)
        t[ty + 8 * i][tx] = W[((size_t)e * DIN + k0 + ty + 8 * i) * DOUT + n0 + tx];
    __syncthreads();
#pragma unroll
    for (int i = 0; i < 4; ++i)
        Wt[((size_t)e * DOUT + n0 + ty + 8 * i) * DIN + k0 + tx] =
            __float2half_rn(t[tx][ty + 8 * i]);
}

// ---------------- routing: per-(expert,k) lists ------------------------------
template<int WHICH>
__global__ void route_kernel(const int* __restrict__ idx,
                             const float* __restrict__ wts,
                             const int* __restrict__ map, int M) {
    int* cnt = g_cnt + WHICH * 16;
    int* rowlist; float* wlist; int cap;
    if      (WHICH == 0) { rowlist = g_rows_node;  wlist = g_w_node;  cap = CAPN2; }
    else if (WHICH == 1) { rowlist = g_rows_edge;  wlist = g_w_edge;  cap = CAPE2; }
    else                 { rowlist = g_rows_angle; wlist = g_w_angle; cap = CAPA2; }

    int i = blockIdx.x * blockDim.x + threadIdx.x;
    if (i >= M) return;
    int src = (WHICH == 0) ? i : map[i];
    int lane = threadIdx.x & 31;

#pragma unroll
    for (int k = 0; k < 2; ++k) {
        int   e = idx[2 * src + k];
        float w = wts[2 * src + k];
        int   li = e * 2 + k;                       // list index 0..15
        unsigned mask = __match_any_sync(0xffffffffu, e);
        int leader = __ffs(mask) - 1;
        int rank   = __popc(mask & ((1u << lane) - 1u));
        int base = 0;
        if (lane == leader) base = atomicAdd(&cnt[li], __popc(mask));
        base = __shfl_sync(mask, base, leader);
        int p = base + rank;
        if (p > cap - 1) p = cap - 1;     // statistically impossible; keep in bounds
        int flat = li * cap + p;
        rowlist[flat] = i;
        wlist[flat]   = w;
    }
}

// ---------------- grouped HMMA GEMM -----------------------------------------
// 64 rows x full DOUT per CTA, 256 threads = 8 warps (2m x 4n), BK=32.
// K-major smem, 80B rows (conflict-free ldmatrix). A loaded fp32 (gathered
// once per slot) and converted fp16 during the fill; register prefetch
// overlaps next chunk's LDGs with current MMAs (proven R10 loop).
// Epilogue: KS==0 -> plain float2 stores (writes every row once);
//           KS==1 -> load+add+store (stream-ordered after pass A, race-free).
template<int WHICH, int KS>
__global__ void __launch_bounds__(256)
moe_gemm_mma(const float* __restrict__ X, const float* __restrict__ Bias,
             float* __restrict__ Out) {
    constexpr int DIN  = (WHICH == 0) ? ND : (WHICH == 1) ? NSYM : (WHICH == 2) ? EINFO : ADIM;
    constexpr int DOUT = (WHICH <= 1) ? DO_NODE : (WHICH == 2) ? DO_EDGE : DO_ANGLE;
    constexpr int CAP  = (WHICH <= 1) ? CAPN2 : (WHICH == 2) ? CAPE2 : CAPA2;
    constexpr int WN   = DOUT / 4;       // cols per warp band
    constexpr int FN   = WN / 8;         // n fragments per warp (4/6/3)
    constexpr int NCH  = DIN / 32;

    const __half* Wt;
    const int* rowlist; const float* wlist;
    if (WHICH == 0) { Wt = g_w1t; rowlist = g_rows_node;  wlist = g_w_node;  }
    if (WHICH == 1) { Wt = g_w2t; rowlist = g_rows_node;  wlist = g_w_node;  }
    if (WHICH == 2) { Wt = g_wet; rowlist = g_rows_edge;  wlist = g_w_edge;  }
    if (WHICH == 3) { Wt = g_wat; rowlist = g_rows_angle; wlist = g_w_angle; }
    const int which_r = (WHICH <= 1) ? 0 : (WHICH - 1);

    const int e  = blockIdx.y;
    const int li = e * 2 + KS;
    int count = min(g_cnt[which_r * 16 + li], CAP);
    const int m0 = blockIdx.x * 64;
    if (m0 >= count) return;

    __shared__ __align__(16) __half As[64 * 40];     // 64 rows x 80B
    __shared__ __align__(16) __half Bs[DOUT * 40];   // DOUT rows x 80B
    __shared__ int   srow[64];
    __shared__ float swt[64];

    const int tid  = threadIdx.x;
    const int wid  = tid >> 5;
    const int lane = tid & 31;
    const int warp_m = wid & 1;        // 0..1 -> 32-row band
    const int warp_n = wid >> 1;       // 0..3 -> WN-col band

    if (tid < 64) {
        int m = m0 + tid;
        if (m < count) { srow[tid] = rowlist[li * CAP + m]; swt[tid] = wlist[li * CAP + m]; }
        else           { srow[tid] = rowlist[li * CAP];     swt[tid] = 0.f; }
    }
    __syncthreads();

    // A fill: 4 threads per row, 8 fp32 each per 32-chunk
    const int arow = tid >> 2;          // 0..63
    const int aseg = tid & 3;           // 8-float segment
    const float* aptr = X + (size_t)srow[arow] * DIN + aseg * 8;
    const bool bval = tid < DOUT;
    const __half* bptr = Wt + ((size_t)e * DOUT + (bval ? tid : 0)) * DIN;

    const uint32_t As_u = smem_u32(As), Bs_u = smem_u32(Bs);
    const uint32_t a_st = As_u + (uint32_t)arow * 80u + (uint32_t)aseg * 16u;
    const uint32_t b_st = Bs_u + (uint32_t)tid * 80u;
    const uint32_t a_ld = As_u + (uint32_t)(warp_m * 32 + (lane & 15)) * 80u
                          + (uint32_t)(lane >> 4) * 16u;
    const uint32_t b_ld = Bs_u + (uint32_t)(warp_n * WN + (lane & 7)) * 80u
                          + (uint32_t)((lane >> 3) & 1) * 16u;

    float acc[2][FN][4];
#pragma unroll
    for (int i = 0; i < 2; ++i)
#pragma unroll
        for (int j = 0; j < FN; ++j)
#pragma unroll
            for (int q = 0; q < 4; ++q) acc[i][j][q] = 0.f;

    float4 ar[2];
    uint4  br[4];

    // prologue prefetch (chunk 0)
    ar[0] = *reinterpret_cast<const float4*>(aptr);
    ar[1] = *reinterpret_cast<const float4*>(aptr + 4);
    if (bval) {
#pragma unroll
        for (int j = 0; j < 4; ++j) br[j] = *reinterpret_cast<const uint4*>(bptr + j * 8);
    }

    for (int c = 0; c < NCH; ++c) {
        __syncthreads();    // previous chunk's ldmatrix reads complete
        {
            uint32_t u0 = h2b(__floats2half2_rn(ar[0].x, ar[0].y));
            uint32_t u1 = h2b(__floats2half2_rn(ar[0].z, ar[0].w));
            uint32_t u2 = h2b(__floats2half2_rn(ar[1].x, ar[1].y));
            uint32_t u3 = h2b(__floats2half2_rn(ar[1].z, ar[1].w));
            STS128(a_st, u0, u1, u2, u3);
        }
        if (bval) {
#pragma unroll
            for (int j = 0; j < 4; ++j)
                STS128(b_st + (uint32_t)j * 16u, br[j].x, br[j].y, br[j].z, br[j].w);
        }
        __syncthreads();
        // prefetch next chunk (LDG latency overlaps MMA below)
        if (c + 1 < NCH) {
            ar[0] = *reinterpret_cast<const float4*>(aptr + (c + 1) * 32);
            ar[1] = *reinterpret_cast<const float4*>(aptr + (c + 1) * 32 + 4);
            if (bval) {
#pragma unroll
                for (int j = 0; j < 4; ++j)
                    br[j] = *reinterpret_cast<const uint4*>(bptr + (c + 1) * 32 + j * 8);
            }
        }
#pragma unroll
        for (int kk = 0; kk < 2; ++kk) {
            uint32_t a[2][4], b[FN][2];
#pragma unroll
            for (int fm = 0; fm < 2; ++fm)
                LDMATRIX_X4(a[fm][0], a[fm][1], a[fm][2], a[fm][3],
                            a_ld + (uint32_t)fm * 16u * 80u + (uint32_t)kk * 32u);
#pragma unroll
            for (int fn = 0; fn < FN; ++fn)
                LDMATRIX_X2(b[fn][0], b[fn][1],
                            b_ld + (uint32_t)fn * 8u * 80u + (uint32_t)kk * 32u);
#pragma unroll
            for (int fm = 0; fm < 2; ++fm)
#pragma unroll
                for (int fn = 0; fn < FN; ++fn)
                    MMA_16816(acc[fm][fn], a[fm], b[fn]);
        }
    }

    // epilogue: bias + silu + topk-weight
    const int qrow = lane >> 2;
    const int qcol = (lane & 3) * 2;
    const float* be = Bias + e * DOUT;
#pragma unroll
    for (int fm = 0; fm < 2; ++fm) {
#pragma unroll
        for (int hf = 0; hf < 2; ++hf) {
            int rloc = warp_m * 32 + fm * 16 + hf * 8 + qrow;
            int m = m0 + rloc;
            if (m >= count) continue;
            float wt = swt[rloc];
            float* orow = Out + (size_t)srow[rloc] * DOUT;
#pragma unroll
            for (int fn = 0; fn < FN; ++fn) {
                int col = warp_n * WN + fn * 8 + qcol;
                float h0 = acc[fm][fn][hf * 2 + 0] + be[col];
                float h1 = acc[fm][fn][hf * 2 + 1] + be[col + 1];
                float s0 = wt * (h0 / (1.f + __expf(-h0)));
                float s1 = wt * (h1 / (1.f + __expf(-h1)));
                if (KS == 0) {
                    *reinterpret_cast<float2*>(orow + col) = make_float2(s0, s1);
                } else {
                    float2 prev = *reinterpret_cast<const float2*>(orow + col);
                    *reinterpret_cast<float2*>(orow + col) =
                        make_float2(prev.x + s0, prev.y + s1);
                }
            }
        }
    }
}

// ---------------- launch ----------------------------------------------------
extern "C" void kernel_launch(void* const* d_in, const int* in_sizes, int n_in,
                              void* d_out, int out_size) {
    const float* x_m1 = (const float*)d_in[0];
    const float* x_m2 = (const float*)d_in[1];
    const float* x_e  = (const float*)d_in[2];
    const float* x_a  = (const float*)d_in[3];
    const float* nw   = (const float*)d_in[4];
    const int*   ni   = (const int*)  d_in[5];
    const float* ewn  = (const float*)d_in[6];
    const int*   ein  = (const int*)  d_in[7];
    const float* awn  = (const float*)d_in[8];
    const int*   ain  = (const int*)  d_in[9];
    const int*   n2e  = (const int*)  d_in[10];
    const int*   n2a  = (const int*)  d_in[11];
    const float* W1 = (const float*)d_in[12];
    const float* b1 = (const float*)d_in[13];
    const float* W2 = (const float*)d_in[14];
    const float* b2 = (const float*)d_in[15];
    const float* We = (const float*)d_in[16];
    const float* be = (const float*)d_in[17];
    const float* Wa = (const float*)d_in[18];
    const float* ba = (const float*)d_in[19];
    float* out = (float*)d_out;
    (void)in_sizes; (void)n_in; (void)out_size;

    // 1) zero counters; weight transpose/convert
    init_kernel<<<1, 64>>>();
    wcvt_kernel<0><<<dim3((ND   / 32) * (DO_NODE  / 32), 8), dim3(32, 8)>>>(W1);
    wcvt_kernel<1><<<dim3((NSYM / 32) * (DO_NODE  / 32), 8), dim3(32, 8)>>>(W2);
    wcvt_kernel<2><<<dim3((EINFO/ 32) * (DO_EDGE  / 32), 8), dim3(32, 8)>>>(We);
    wcvt_kernel<3><<<dim3((ADIM / 32) * (DO_ANGLE / 32), 8), dim3(32, 8)>>>(Wa);

    // 2) routing (per-(expert,k) lists)
    route_kernel<0><<<N_NODE  / 256, 256>>>(ni,  nw,  nullptr, N_NODE);
    route_kernel<1><<<N_EDGE  / 256, 256>>>(ein, ewn, n2e,     N_EDGE);
    route_kernel<2><<<N_ANGLE / 256, 256>>>(ain, awn, n2a,     N_ANGLE);

    // 3) pass A: k=0 slots, plain stores (write every output row once)
    moe_gemm_mma<3, 0><<<dim3(CAPA2 / 64, 8), 256>>>(x_a,  ba, out + OUT_ANGLE);
    moe_gemm_mma<2, 0><<<dim3(CAPE2 / 64, 8), 256>>>(x_e,  be, out + OUT_EDGE);
    moe_gemm_mma<1, 0><<<dim3(CAPN2 / 64, 8), 256>>>(x_m2, b2, out + OUT_M2);
    moe_gemm_mma<0, 0><<<dim3(CAPN2 / 64, 8), 256>>>(x_m1, b1, out + OUT_M1);

    // 4) pass B: k=1 slots, race-free load+add+store (stream-ordered after A)
    moe_gemm_mma<3, 1><<<dim3(CAPA2 / 64, 8), 256>>>(x_a,  ba, out + OUT_ANGLE);
    moe_gemm_mma<2, 1><<<dim3(CAPE2 / 64, 8), 256>>>(x_e,  be, out + OUT_EDGE);
    moe_gemm_mma<1, 1><<<dim3(CAPN2 / 64, 8), 256>>>(x_m2, b2, out + OUT_M2);
    moe_gemm_mma<0, 1><<<dim3(CAPN2 / 64, 8), 256>>>(x_m1, b1, out + OUT_M1);
}

// round 13
// speedup vs baseline: 1.3170x; 1.3170x over previous
#include <cuda_runtime.h>
#include <cuda_fp16.h>
#include <math.h>
#include <stdint.h>

// ---------------------------------------------------------------------------
// MoE dispatch/combine via mma.sync HMMA (sm_100 target):
//   out[m] = sum_k w[m,k] * silu(x[m] @ W[e(m,k)] + b[e(m,k)])
// R13: R10 (377us champion) reverted, with (a) launch order placing the angle
// GEMM 6th so ncu -s 5 -c 1 finally profiles a GEMM, and (b) BM=128 tiles for
// the angle GEMM only (halves its CTA count / per-chunk overhead; acc regs =
// 48, same pressure as the proven edge config).
// ---------------------------------------------------------------------------

#define N_NODE   8192
#define N_EDGE   65536
#define N_ANGLE  131072
#define ND       128
#define NSYM     768
#define EINFO    320
#define ADIM     128
#define DO_NODE  128
#define DO_EDGE  192
#define DO_ANGLE 96

#define CAPN 4096
#define CAPE 32768
#define CAPA 65536

#define OUT_M1    ((size_t)0)
#define OUT_M2    ((size_t)N_NODE * ND)
#define OUT_EDGE  (OUT_M2 + (size_t)N_NODE * ND)
#define OUT_ANGLE (OUT_EDGE + (size_t)N_EDGE * DO_EDGE)
#define OUT_TOTAL (OUT_ANGLE + (size_t)N_ANGLE * DO_ANGLE)   // 27,262,976 floats

// ---------------- device scratch -------------------------------------------
__device__ int   g_cnt[24];
__device__ __align__(16) int   g_rows_node [8 * CAPN];
__device__ __align__(16) float g_w_node    [8 * CAPN];
__device__ __align__(16) int   g_rows_edge [8 * CAPE];
__device__ __align__(16) float g_w_edge    [8 * CAPE];
__device__ __align__(16) int   g_rows_angle[8 * CAPA];
__device__ __align__(16) float g_w_angle   [8 * CAPA];

// transposed weights: [E][DOUT][DIN] fp16 (K-major rows)
__device__ __align__(16) __half g_w1t[(size_t)8 * DO_NODE  * ND];
__device__ __align__(16) __half g_w2t[(size_t)8 * DO_NODE  * NSYM];
__device__ __align__(16) __half g_wet[(size_t)8 * DO_EDGE  * EINFO];
__device__ __align__(16) __half g_wat[(size_t)8 * DO_ANGLE * ADIM];

// ---------------- helpers ---------------------------------------------------
__device__ __forceinline__ uint32_t smem_u32(const void* p) {
    uint32_t a;
    asm("{ .reg .u64 t; cvta.to.shared.u64 t, %1; cvt.u32.u64 %0, t; }"
        : "=r"(a) : "l"(p));
    return a;
}

__device__ __forceinline__ uint32_t h2b(__half2 h) {
    return *reinterpret_cast<uint32_t*>(&h);
}

#define LDMATRIX_X4(r0, r1, r2, r3, addr) \
    asm volatile("ldmatrix.sync.aligned.m8n8.x4.shared.b16 {%0,%1,%2,%3}, [%4];" \
                 : "=r"(r0), "=r"(r1), "=r"(r2), "=r"(r3) : "r"(addr))

#define LDMATRIX_X2(r0, r1, addr) \
    asm volatile("ldmatrix.sync.aligned.m8n8.x2.shared.b16 {%0,%1}, [%2];" \
                 : "=r"(r0), "=r"(r1) : "r"(addr))

#define MMA_16816(c, a, b) \
    asm volatile("mma.sync.aligned.m16n8k16.row.col.f32.f16.f16.f32 " \
                 "{%0,%1,%2,%3}, {%4,%5,%6,%7}, {%8,%9}, {%0,%1,%2,%3};" \
                 : "+f"((c)[0]), "+f"((c)[1]), "+f"((c)[2]), "+f"((c)[3]) \
                 : "r"((a)[0]), "r"((a)[1]), "r"((a)[2]), "r"((a)[3]), \
                   "r"((b)[0]), "r"((b)[1]))

#define STS128(addr, v0, v1, v2, v3) \
    asm volatile("st.shared.v4.b32 [%0], {%1,%2,%3,%4};" \
                 :: "r"(addr), "r"(v0), "r"(v1), "r"(v2), "r"(v3) : "memory")

// ---------------- init: zero outputs + counters ------------------------------
__global__ void init_kernel(float* __restrict__ out, int n4) {
    int i = blockIdx.x * blockDim.x + threadIdx.x;
    if (i < n4) reinterpret_cast<float4*>(out)[i] = make_float4(0.f, 0.f, 0.f, 0.f);
    if (i < 24) g_cnt[i] = 0;
}

// ---------------- coalesced transpose+convert weights -----------------------
template<int WHICH>
__global__ void wcvt_kernel(const float* __restrict__ W) {
    constexpr int DIN  = (WHICH == 0) ? ND : (WHICH == 1) ? NSYM : (WHICH == 2) ? EINFO : ADIM;
    constexpr int DOUT = (WHICH <= 1) ? DO_NODE : (WHICH == 2) ? DO_EDGE : DO_ANGLE;
    __half* Wt;
    if      (WHICH == 0) Wt = g_w1t;
    else if (WHICH == 1) Wt = g_w2t;
    else if (WHICH == 2) Wt = g_wet;
    else                 Wt = g_wat;

    __shared__ float t[32][33];
    const int e  = blockIdx.y;
    const int nk = DIN / 32;
    const int k0 = (blockIdx.x % nk) * 32;
    const int n0 = (blockIdx.x / nk) * 32;
    const int tx = threadIdx.x, ty = threadIdx.y;
#pragma unroll
    for (int i = 0; i < 4; ++i)
        t[ty + 8 * i][tx] = W[((size_t)e * DIN + k0 + ty + 8 * i) * DOUT + n0 + tx];
    __syncthreads();
#pragma unroll
    for (int i = 0; i < 4; ++i)
        Wt[((size_t)e * DOUT + n0 + ty + 8 * i) * DIN + k0 + tx] =
            __float2half_rn(t[tx][ty + 8 * i]);
}

// ---------------- routing ---------------------------------------------------
template<int WHICH>
__global__ void route_kernel(const int* __restrict__ idx,
                             const float* __restrict__ wts,
                             const int* __restrict__ map, int M) {
    int* cnt = g_cnt + WHICH * 8;
    int* rowlist; float* wlist; int cap;
    if      (WHICH == 0) { rowlist = g_rows_node;  wlist = g_w_node;  cap = CAPN; }
    else if (WHICH == 1) { rowlist = g_rows_edge;  wlist = g_w_edge;  cap = CAPE; }
    else                 { rowlist = g_rows_angle; wlist = g_w_angle; cap = CAPA; }

    int i = blockIdx.x * blockDim.x + threadIdx.x;
    if (i >= M) return;
    int src = (WHICH == 0) ? i : map[i];
    int lane = threadIdx.x & 31;

#pragma unroll
    for (int k = 0; k < 2; ++k) {
        int   e = idx[2 * src + k];
        float w = wts[2 * src + k];
        unsigned mask = __match_any_sync(0xffffffffu, e);
        int leader = __ffs(mask) - 1;
        int rank   = __popc(mask & ((1u << lane) - 1u));
        int base = 0;
        if (lane == leader) base = atomicAdd(&cnt[e], __popc(mask));
        base = __shfl_sync(mask, base, leader);
        int p = base + rank;
        if (p > cap - 1) p = cap - 1;     // statistically impossible; keep in bounds
        int flat = e * cap + p;
        rowlist[flat] = i;
        wlist[flat]   = w;
    }
}

// ---------------- grouped HMMA GEMM -----------------------------------------
// BM rows x full DOUT per CTA, 256 threads. BM=64 -> 2m x 4n warps;
// BM=128 (angle) -> 4m x 2n. BK=32, K-major smem, 80B rows (conflict-free
// ldmatrix). A loaded fp32 (gathered once) and converted fp16 during the
// fill; register prefetch overlaps next chunk's LDGs with current MMAs.
// Epilogue: bias + silu + topk-weight, fp32 atomicAdd into pre-zeroed output.
template<int WHICH>
__global__ void __launch_bounds__(256)
moe_gemm_mma(const float* __restrict__ X, const float* __restrict__ Bias,
             float* __restrict__ Out) {
    constexpr int DIN  = (WHICH == 0) ? ND : (WHICH == 1) ? NSYM : (WHICH == 2) ? EINFO : ADIM;
    constexpr int DOUT = (WHICH <= 1) ? DO_NODE : (WHICH == 2) ? DO_EDGE : DO_ANGLE;
    constexpr int CAP  = (WHICH <= 1) ? CAPN : (WHICH == 2) ? CAPE : CAPA;
    constexpr int BM   = (WHICH == 3) ? 128 : 64;    // tile rows
    constexpr int NWM  = BM / 32;        // warps along M (2 or 4)
    constexpr int NWN  = 8 / NWM;        // warps along N (4 or 2)
    constexpr int WN   = DOUT / NWN;     // cols per warp band
    constexpr int FN   = WN / 8;         // n fragments per warp
    constexpr int NCH  = DIN / 32;
    constexpr int TPR  = 256 / BM;       // threads per A row (4 or 2)
    constexpr int F4   = 8 / TPR;        // float4 A loads per thread (2 or 4)

    const __half* Wt;
    const int* rowlist; const float* wlist;
    if (WHICH == 0) { Wt = g_w1t; rowlist = g_rows_node;  wlist = g_w_node;  }
    if (WHICH == 1) { Wt = g_w2t; rowlist = g_rows_node;  wlist = g_w_node;  }
    if (WHICH == 2) { Wt = g_wet; rowlist = g_rows_edge;  wlist = g_w_edge;  }
    if (WHICH == 3) { Wt = g_wat; rowlist = g_rows_angle; wlist = g_w_angle; }
    const int which_r = (WHICH <= 1) ? 0 : (WHICH - 1);

    const int e = blockIdx.y;
    int count = min(g_cnt[which_r * 8 + e], CAP);
    const int m0 = blockIdx.x * BM;
    if (m0 >= count) return;

    __shared__ __align__(16) __half As[BM * 40];     // BM rows x 80B
    __shared__ __align__(16) __half Bs[DOUT * 40];   // DOUT rows x 80B
    __shared__ int   srow[BM];
    __shared__ float swt[BM];

    const int tid  = threadIdx.x;
    const int wid  = tid >> 5;
    const int lane = tid & 31;
    const int warp_m = wid % NWM;
    const int warp_n = wid / NWM;

    for (int t = tid; t < BM; t += 256) {
        int m = m0 + t;
        if (m < count) { srow[t] = rowlist[e * CAP + m]; swt[t] = wlist[e * CAP + m]; }
        else           { srow[t] = rowlist[e * CAP];     swt[t] = 0.f; }
    }
    __syncthreads();

    // A fill: TPR threads per row, F4 float4 loads each per 32-chunk
    const int arow = tid / TPR;
    const int aseg = tid % TPR;
    const float* aptr = X + (size_t)srow[arow] * DIN + aseg * (F4 * 4);
    const bool bval = tid < DOUT;
    const __half* bptr = Wt + ((size_t)e * DOUT + (bval ? tid : 0)) * DIN;

    const uint32_t As_u = smem_u32(As), Bs_u = smem_u32(Bs);
    const uint32_t a_st = As_u + (uint32_t)arow * 80u + (uint32_t)(aseg * F4 * 8);
    const uint32_t b_st = Bs_u + (uint32_t)tid * 80u;
    const uint32_t a_ld = As_u + (uint32_t)(warp_m * 32 + (lane & 15)) * 80u
                          + (uint32_t)(lane >> 4) * 16u;
    const uint32_t b_ld = Bs_u + (uint32_t)(warp_n * WN + (lane & 7)) * 80u
                          + (uint32_t)((lane >> 3) & 1) * 16u;

    float acc[2][FN][4];
#pragma unroll
    for (int i = 0; i < 2; ++i)
#pragma unroll
        for (int j = 0; j < FN; ++j)
#pragma unroll
            for (int q = 0; q < 4; ++q) acc[i][j][q] = 0.f;

    float4 ar[F4];
    uint4  br[4];

    // prologue prefetch (chunk 0)
#pragma unroll
    for (int j = 0; j < F4; ++j)
        ar[j] = *reinterpret_cast<const float4*>(aptr + j * 4);
    if (bval) {
#pragma unroll
        for (int j = 0; j < 4; ++j) br[j] = *reinterpret_cast<const uint4*>(bptr + j * 8);
    }

    for (int c = 0; c < NCH; ++c) {
        __syncthreads();    // previous chunk's ldmatrix reads complete
#pragma unroll
        for (int j = 0; j < F4; j += 2) {
            uint32_t u0 = h2b(__floats2half2_rn(ar[j].x,     ar[j].y));
            uint32_t u1 = h2b(__floats2half2_rn(ar[j].z,     ar[j].w));
            uint32_t u2 = h2b(__floats2half2_rn(ar[j + 1].x, ar[j + 1].y));
            uint32_t u3 = h2b(__floats2half2_rn(ar[j + 1].z, ar[j + 1].w));
            STS128(a_st + (uint32_t)(j / 2) * 16u, u0, u1, u2, u3);
        }
        if (bval) {
#pragma unroll
            for (int j = 0; j < 4; ++j)
                STS128(b_st + (uint32_t)j * 16u, br[j].x, br[j].y, br[j].z, br[j].w);
        }
        __syncthreads();
        // prefetch next chunk (LDG latency overlaps MMA below)
        if (c + 1 < NCH) {
#pragma unroll
            for (int j = 0; j < F4; ++j)
                ar[j] = *reinterpret_cast<const float4*>(aptr + (c + 1) * 32 + j * 4);
            if (bval) {
#pragma unroll
                for (int j = 0; j < 4; ++j)
                    br[j] = *reinterpret_cast<const uint4*>(bptr + (c + 1) * 32 + j * 8);
            }
        }
#pragma unroll
        for (int kk = 0; kk < 2; ++kk) {
            uint32_t a[2][4], b[FN][2];
#pragma unroll
            for (int fm = 0; fm < 2; ++fm)
                LDMATRIX_X4(a[fm][0], a[fm][1], a[fm][2], a[fm][3],
                            a_ld + (uint32_t)fm * 16u * 80u + (uint32_t)kk * 32u);
#pragma unroll
            for (int fn = 0; fn < FN; ++fn)
                LDMATRIX_X2(b[fn][0], b[fn][1],
                            b_ld + (uint32_t)fn * 8u * 80u + (uint32_t)kk * 32u);
#pragma unroll
            for (int fm = 0; fm < 2; ++fm)
#pragma unroll
                for (int fn = 0; fn < FN; ++fn)
                    MMA_16816(acc[fm][fn], a[fm], b[fn]);
        }
    }

    // epilogue: bias + silu + topk-weight -> fp32 atomicAdd into output
    const int qrow = lane >> 2;
    const int qcol = (lane & 3) * 2;
    const float* be = Bias + e * DOUT;
#pragma unroll
    for (int fm = 0; fm < 2; ++fm) {
#pragma unroll
        for (int hf = 0; hf < 2; ++hf) {
            int rloc = warp_m * 32 + fm * 16 + hf * 8 + qrow;
            int m = m0 + rloc;
            if (m >= count) continue;
            float wt = swt[rloc];
            float* orow = Out + (size_t)srow[rloc] * DOUT;
#pragma unroll
            for (int fn = 0; fn < FN; ++fn) {
                int col = warp_n * WN + fn * 8 + qcol;
                float h0 = acc[fm][fn][hf * 2 + 0] + be[col];
                float h1 = acc[fm][fn][hf * 2 + 1] + be[col + 1];
                atomicAdd(orow + col,     wt * (h0 / (1.f + __expf(-h0))));
                atomicAdd(orow + col + 1, wt * (h1 / (1.f + __expf(-h1))));
            }
        }
    }
}

// ---------------- launch ----------------------------------------------------
extern "C" void kernel_launch(void* const* d_in, const int* in_sizes, int n_in,
                              void* d_out, int out_size) {
    const float* x_m1 = (const float*)d_in[0];
    const float* x_m2 = (const float*)d_in[1];
    const float* x_e  = (const float*)d_in[2];
    const float* x_a  = (const float*)d_in[3];
    const float* nw   = (const float*)d_in[4];
    const int*   ni   = (const int*)  d_in[5];
    const float* ewn  = (const float*)d_in[6];
    const int*   ein  = (const int*)  d_in[7];
    const float* awn  = (const float*)d_in[8];
    const int*   ain  = (const int*)  d_in[9];
    const int*   n2e  = (const int*)  d_in[10];
    const int*   n2a  = (const int*)  d_in[11];
    const float* W1 = (const float*)d_in[12];
    const float* b1 = (const float*)d_in[13];
    const float* W2 = (const float*)d_in[14];
    const float* b2 = (const float*)d_in[15];
    const float* We = (const float*)d_in[16];
    const float* be = (const float*)d_in[17];
    const float* Wa = (const float*)d_in[18];
    const float* ba = (const float*)d_in[19];
    float* out = (float*)d_out;
    (void)in_sizes; (void)n_in; (void)out_size;

    int n4 = (int)(OUT_TOTAL / 4);

    // Launch order chosen so ncu (-s 5 -c 1) profiles the angle GEMM (6th):
    // 1 init, 2-4 routing, 5 wcvt<3>, 6 gemm<3>, then the rest.
    init_kernel<<<(n4 + 255) / 256, 256>>>(out, n4);                       // 1
    route_kernel<0><<<N_NODE  / 256, 256>>>(ni,  nw,  nullptr, N_NODE);    // 2
    route_kernel<1><<<N_EDGE  / 256, 256>>>(ein, ewn, n2e,     N_EDGE);    // 3
    route_kernel<2><<<N_ANGLE / 256, 256>>>(ain, awn, n2a,     N_ANGLE);   // 4
    wcvt_kernel<3><<<dim3((ADIM / 32) * (DO_ANGLE / 32), 8), dim3(32, 8)>>>(Wa); // 5
    moe_gemm_mma<3><<<dim3(CAPA / 128, 8), 256>>>(x_a,  ba, out + OUT_ANGLE);    // 6 (profiled)
    wcvt_kernel<2><<<dim3((EINFO/ 32) * (DO_EDGE  / 32), 8), dim3(32, 8)>>>(We);
    moe_gemm_mma<2><<<dim3(CAPE / 64, 8), 256>>>(x_e,  be, out + OUT_EDGE);
    wcvt_kernel<1><<<dim3((NSYM / 32) * (DO_NODE  / 32), 8), dim3(32, 8)>>>(W2);
    moe_gemm_mma<1><<<dim3(CAPN / 64, 8), 256>>>(x_m2, b2, out + OUT_M2);
    wcvt_kernel<0><<<dim3((ND   / 32) * (DO_NODE  / 32), 8), dim3(32, 8)>>>(W1);
    moe_gemm_mma<0><<<dim3(CAPN / 64, 8), 256>>>(x_m1, b1, out + OUT_M1);
}

// round 14
// speedup vs baseline: 1.4112x; 1.0715x over previous
#include <cuda_runtime.h>
#include <cuda_fp16.h>
#include <math.h>
#include <stdint.h>

// ---------------------------------------------------------------------------
// MoE dispatch/combine via mma.sync HMMA (sm_100 target):
//   out[m] = sum_k w[m,k] * silu(x[m] @ W[e(m,k)] + b[e(m,k)])
// R14: R13 + edge GEMM widened to BM=128 via 512-thread CTAs (4m x 4n warps;
// per-thread pressure identical to the proven edge config). Halves edge CTA
// count / per-tile overhead, the same lever that won for angle in R13.
// ---------------------------------------------------------------------------

#define N_NODE   8192
#define N_EDGE   65536
#define N_ANGLE  131072
#define ND       128
#define NSYM     768
#define EINFO    320
#define ADIM     128
#define DO_NODE  128
#define DO_EDGE  192
#define DO_ANGLE 96

#define CAPN 4096
#define CAPE 32768
#define CAPA 65536

#define OUT_M1    ((size_t)0)
#define OUT_M2    ((size_t)N_NODE * ND)
#define OUT_EDGE  (OUT_M2 + (size_t)N_NODE * ND)
#define OUT_ANGLE (OUT_EDGE + (size_t)N_EDGE * DO_EDGE)
#define OUT_TOTAL (OUT_ANGLE + (size_t)N_ANGLE * DO_ANGLE)   // 27,262,976 floats

// ---------------- device scratch -------------------------------------------
__device__ int   g_cnt[24];
__device__ __align__(16) int   g_rows_node [8 * CAPN];
__device__ __align__(16) float g_w_node    [8 * CAPN];
__device__ __align__(16) int   g_rows_edge [8 * CAPE];
__device__ __align__(16) float g_w_edge    [8 * CAPE];
__device__ __align__(16) int   g_rows_angle[8 * CAPA];
__device__ __align__(16) float g_w_angle   [8 * CAPA];

// transposed weights: [E][DOUT][DIN] fp16 (K-major rows)
__device__ __align__(16) __half g_w1t[(size_t)8 * DO_NODE  * ND];
__device__ __align__(16) __half g_w2t[(size_t)8 * DO_NODE  * NSYM];
__device__ __align__(16) __half g_wet[(size_t)8 * DO_EDGE  * EINFO];
__device__ __align__(16) __half g_wat[(size_t)8 * DO_ANGLE * ADIM];

// ---------------- helpers ---------------------------------------------------
__device__ __forceinline__ uint32_t smem_u32(const void* p) {
    uint32_t a;
    asm("{ .reg .u64 t; cvta.to.shared.u64 t, %1; cvt.u32.u64 %0, t; }"
        : "=r"(a) : "l"(p));
    return a;
}

__device__ __forceinline__ uint32_t h2b(__half2 h) {
    return *reinterpret_cast<uint32_t*>(&h);
}

#define LDMATRIX_X4(r0, r1, r2, r3, addr) \
    asm volatile("ldmatrix.sync.aligned.m8n8.x4.shared.b16 {%0,%1,%2,%3}, [%4];" \
                 : "=r"(r0), "=r"(r1), "=r"(r2), "=r"(r3) : "r"(addr))

#define LDMATRIX_X2(r0, r1, addr) \
    asm volatile("ldmatrix.sync.aligned.m8n8.x2.shared.b16 {%0,%1}, [%2];" \
                 : "=r"(r0), "=r"(r1) : "r"(addr))

#define MMA_16816(c, a, b) \
    asm volatile("mma.sync.aligned.m16n8k16.row.col.f32.f16.f16.f32 " \
                 "{%0,%1,%2,%3}, {%4,%5,%6,%7}, {%8,%9}, {%0,%1,%2,%3};" \
                 : "+f"((c)[0]), "+f"((c)[1]), "+f"((c)[2]), "+f"((c)[3]) \
                 : "r"((a)[0]), "r"((a)[1]), "r"((a)[2]), "r"((a)[3]), \
                   "r"((b)[0]), "r"((b)[1]))

#define STS128(addr, v0, v1, v2, v3) \
    asm volatile("st.shared.v4.b32 [%0], {%1,%2,%3,%4};" \
                 :: "r"(addr), "r"(v0), "r"(v1), "r"(v2), "r"(v3) : "memory")

// ---------------- init: zero outputs + counters ------------------------------
__global__ void init_kernel(float* __restrict__ out, int n4) {
    int i = blockIdx.x * blockDim.x + threadIdx.x;
    if (i < n4) reinterpret_cast<float4*>(out)[i] = make_float4(0.f, 0.f, 0.f, 0.f);
    if (i < 24) g_cnt[i] = 0;
}

// ---------------- coalesced transpose+convert weights -----------------------
template<int WHICH>
__global__ void wcvt_kernel(const float* __restrict__ W) {
    constexpr int DIN  = (WHICH == 0) ? ND : (WHICH == 1) ? NSYM : (WHICH == 2) ? EINFO : ADIM;
    constexpr int DOUT = (WHICH <= 1) ? DO_NODE : (WHICH == 2) ? DO_EDGE : DO_ANGLE;
    __half* Wt;
    if      (WHICH == 0) Wt = g_w1t;
    else if (WHICH == 1) Wt = g_w2t;
    else if (WHICH == 2) Wt = g_wet;
    else                 Wt = g_wat;

    __shared__ float t[32][33];
    const int e  = blockIdx.y;
    const int nk = DIN / 32;
    const int k0 = (blockIdx.x % nk) * 32;
    const int n0 = (blockIdx.x / nk) * 32;
    const int tx = threadIdx.x, ty = threadIdx.y;
#pragma unroll
    for (int i = 0; i < 4; ++i)
        t[ty + 8 * i][tx] = W[((size_t)e * DIN + k0 + ty + 8 * i) * DOUT + n0 + tx];
    __syncthreads();
#pragma unroll
    for (int i = 0; i < 4; ++i)
        Wt[((size_t)e * DOUT + n0 + ty + 8 * i) * DIN + k0 + tx] =
            __float2half_rn(t[tx][ty + 8 * i]);
}

// ---------------- routing ---------------------------------------------------
template<int WHICH>
__global__ void route_kernel(const int* __restrict__ idx,
                             const float* __restrict__ wts,
                             const int* __restrict__ map, int M) {
    int* cnt = g_cnt + WHICH * 8;
    int* rowlist; float* wlist; int cap;
    if      (WHICH == 0) { rowlist = g_rows_node;  wlist = g_w_node;  cap = CAPN; }
    else if (WHICH == 1) { rowlist = g_rows_edge;  wlist = g_w_edge;  cap = CAPE; }
    else                 { rowlist = g_rows_angle; wlist = g_w_angle; cap = CAPA; }

    int i = blockIdx.x * blockDim.x + threadIdx.x;
    if (i >= M) return;
    int src = (WHICH == 0) ? i : map[i];
    int lane = threadIdx.x & 31;

#pragma unroll
    for (int k = 0; k < 2; ++k) {
        int   e = idx[2 * src + k];
        float w = wts[2 * src + k];
        unsigned mask = __match_any_sync(0xffffffffu, e);
        int leader = __ffs(mask) - 1;
        int rank   = __popc(mask & ((1u << lane) - 1u));
        int base = 0;
        if (lane == leader) base = atomicAdd(&cnt[e], __popc(mask));
        base = __shfl_sync(mask, base, leader);
        int p = base + rank;
        if (p > cap - 1) p = cap - 1;     // statistically impossible; keep in bounds
        int flat = e * cap + p;
        rowlist[flat] = i;
        wlist[flat]   = w;
    }
}

// ---------------- grouped HMMA GEMM -----------------------------------------
// BM rows x full DOUT per CTA, NT threads. Warp grid NWM x NWN covers
// (NWM*32) x DOUT. BK=32, K-major smem, 80B rows (conflict-free ldmatrix).
// A loaded fp32 (gathered once) and converted fp16 during the fill; register
// prefetch overlaps next chunk's LDGs with current MMAs. Epilogue: bias +
// silu + topk-weight, fp32 atomicAdd into pre-zeroed output.
// Configs: node m1/m2 (256t, BM=64, 2x4), edge (512t, BM=128, 4x4),
//          angle (256t, BM=128, 4x2). Per-thread acc <= 48 regs everywhere.
template<int WHICH>
__global__ void __launch_bounds__((WHICH == 2) ? 512 : 256)
moe_gemm_mma(const float* __restrict__ X, const float* __restrict__ Bias,
             float* __restrict__ Out) {
    constexpr int DIN  = (WHICH == 0) ? ND : (WHICH == 1) ? NSYM : (WHICH == 2) ? EINFO : ADIM;
    constexpr int DOUT = (WHICH <= 1) ? DO_NODE : (WHICH == 2) ? DO_EDGE : DO_ANGLE;
    constexpr int CAP  = (WHICH <= 1) ? CAPN : (WHICH == 2) ? CAPE : CAPA;
    constexpr int NT   = (WHICH == 2) ? 512 : 256;   // threads
    constexpr int BM   = (WHICH >= 2) ? 128 : 64;    // tile rows
    constexpr int NWM  = BM / 32;        // warps along M
    constexpr int NWN  = (NT / 32) / NWM;            // warps along N
    constexpr int WN   = DOUT / NWN;     // cols per warp band
    constexpr int FN   = WN / 8;         // n fragments per warp (<=6)
    constexpr int NCH  = DIN / 32;
    constexpr int TPR  = NT / BM;        // threads per A row (4 or 2)
    constexpr int F4   = 8 / TPR;        // float4 A loads per thread

    const __half* Wt;
    const int* rowlist; const float* wlist;
    if (WHICH == 0) { Wt = g_w1t; rowlist = g_rows_node;  wlist = g_w_node;  }
    if (WHICH == 1) { Wt = g_w2t; rowlist = g_rows_node;  wlist = g_w_node;  }
    if (WHICH == 2) { Wt = g_wet; rowlist = g_rows_edge;  wlist = g_w_edge;  }
    if (WHICH == 3) { Wt = g_wat; rowlist = g_rows_angle; wlist = g_w_angle; }
    const int which_r = (WHICH <= 1) ? 0 : (WHICH - 1);

    const int e = blockIdx.y;
    int count = min(g_cnt[which_r * 8 + e], CAP);
    const int m0 = blockIdx.x * BM;
    if (m0 >= count) return;

    __shared__ __align__(16) __half As[BM * 40];     // BM rows x 80B
    __shared__ __align__(16) __half Bs[DOUT * 40];   // DOUT rows x 80B
    __shared__ int   srow[BM];
    __shared__ float swt[BM];

    const int tid  = threadIdx.x;
    const int wid  = tid >> 5;
    const int lane = tid & 31;
    const int warp_m = wid % NWM;
    const int warp_n = wid / NWM;

    for (int t = tid; t < BM; t += NT) {
        int m = m0 + t;
        if (m < count) { srow[t] = rowlist[e * CAP + m]; swt[t] = wlist[e * CAP + m]; }
        else           { srow[t] = rowlist[e * CAP];     swt[t] = 0.f; }
    }
    __syncthreads();

    // A fill: TPR threads per row, F4 float4 loads each per 32-chunk
    const int arow = tid / TPR;
    const int aseg = tid % TPR;
    const float* aptr = X + (size_t)srow[arow] * DIN + aseg * (F4 * 4);
    const bool bval = tid < DOUT;
    const __half* bptr = Wt + ((size_t)e * DOUT + (bval ? tid : 0)) * DIN;

    const uint32_t As_u = smem_u32(As), Bs_u = smem_u32(Bs);
    const uint32_t a_st = As_u + (uint32_t)arow * 80u + (uint32_t)(aseg * F4 * 8);
    const uint32_t b_st = Bs_u + (uint32_t)tid * 80u;
    const uint32_t a_ld = As_u + (uint32_t)(warp_m * 32 + (lane & 15)) * 80u
                          + (uint32_t)(lane >> 4) * 16u;
    const uint32_t b_ld = Bs_u + (uint32_t)(warp_n * WN + (lane & 7)) * 80u
                          + (uint32_t)((lane >> 3) & 1) * 16u;

    float acc[2][FN][4];
#pragma unroll
    for (int i = 0; i < 2; ++i)
#pragma unroll
        for (int j = 0; j < FN; ++j)
#pragma unroll
            for (int q = 0; q < 4; ++q) acc[i][j][q] = 0.f;

    float4 ar[F4];
    uint4  br[4];

    // prologue prefetch (chunk 0)
#pragma unroll
    for (int j = 0; j < F4; ++j)
        ar[j] = *reinterpret_cast<const float4*>(aptr + j * 4);
    if (bval) {
#pragma unroll
        for (int j = 0; j < 4; ++j) br[j] = *reinterpret_cast<const uint4*>(bptr + j * 8);
    }

    for (int c = 0; c < NCH; ++c) {
        __syncthreads();    // previous chunk's ldmatrix reads complete
#pragma unroll
        for (int j = 0; j < F4; j += 2) {
            uint32_t u0 = h2b(__floats2half2_rn(ar[j].x,     ar[j].y));
            uint32_t u1 = h2b(__floats2half2_rn(ar[j].z,     ar[j].w));
            uint32_t u2 = h2b(__floats2half2_rn(ar[j + 1].x, ar[j + 1].y));
            uint32_t u3 = h2b(__floats2half2_rn(ar[j + 1].z, ar[j + 1].w));
            STS128(a_st + (uint32_t)(j / 2) * 16u, u0, u1, u2, u3);
        }
        if (bval) {
#pragma unroll
            for (int j = 0; j < 4; ++j)
                STS128(b_st + (uint32_t)j * 16u, br[j].x, br[j].y, br[j].z, br[j].w);
        }
        __syncthreads();
        // prefetch next chunk (LDG latency overlaps MMA below)
        if (c + 1 < NCH) {
#pragma unroll
            for (int j = 0; j < F4; ++j)
                ar[j] = *reinterpret_cast<const float4*>(aptr + (c + 1) * 32 + j * 4);
            if (bval) {
#pragma unroll
                for (int j = 0; j < 4; ++j)
                    br[j] = *reinterpret_cast<const uint4*>(bptr + (c + 1) * 32 + j * 8);
            }
        }
#pragma unroll
        for (int kk = 0; kk < 2; ++kk) {
            uint32_t a[2][4], b[FN][2];
#pragma unroll
            for (int fm = 0; fm < 2; ++fm)
                LDMATRIX_X4(a[fm][0], a[fm][1], a[fm][2], a[fm][3],
                            a_ld + (uint32_t)fm * 16u * 80u + (uint32_t)kk * 32u);
#pragma unroll
            for (int fn = 0; fn < FN; ++fn)
                LDMATRIX_X2(b[fn][0], b[fn][1],
                            b_ld + (uint32_t)fn * 8u * 80u + (uint32_t)kk * 32u);
#pragma unroll
            for (int fm = 0; fm < 2; ++fm)
#pragma unroll
                for (int fn = 0; fn < FN; ++fn)
                    MMA_16816(acc[fm][fn], a[fm], b[fn]);
        }
    }

    // epilogue: bias + silu + topk-weight -> fp32 atomicAdd into output
    const int qrow = lane >> 2;
    const int qcol = (lane & 3) * 2;
    const float* be = Bias + e * DOUT;
#pragma unroll
    for (int fm = 0; fm < 2; ++fm) {
#pragma unroll
        for (int hf = 0; hf < 2; ++hf) {
            int rloc = warp_m * 32 + fm * 16 + hf * 8 + qrow;
            int m = m0 + rloc;
            if (m >= count) continue;
            float wt = swt[rloc];
            float* orow = Out + (size_t)srow[rloc] * DOUT;
#pragma unroll
            for (int fn = 0; fn < FN; ++fn) {
                int col = warp_n * WN + fn * 8 + qcol;
                float h0 = acc[fm][fn][hf * 2 + 0] + be[col];
                float h1 = acc[fm][fn][hf * 2 + 1] + be[col + 1];
                atomicAdd(orow + col,     wt * (h0 / (1.f + __expf(-h0))));
                atomicAdd(orow + col + 1, wt * (h1 / (1.f + __expf(-h1))));
            }
        }
    }
}

// ---------------- launch ----------------------------------------------------
extern "C" void kernel_launch(void* const* d_in, const int* in_sizes, int n_in,
                              void* d_out, int out_size) {
    const float* x_m1 = (const float*)d_in[0];
    const float* x_m2 = (const float*)d_in[1];
    const float* x_e  = (const float*)d_in[2];
    const float* x_a  = (const float*)d_in[3];
    const float* nw   = (const float*)d_in[4];
    const int*   ni   = (const int*)  d_in[5];
    const float* ewn  = (const float*)d_in[6];
    const int*   ein  = (const int*)  d_in[7];
    const float* awn  = (const float*)d_in[8];
    const int*   ain  = (const int*)  d_in[9];
    const int*   n2e  = (const int*)  d_in[10];
    const int*   n2a  = (const int*)  d_in[11];
    const float* W1 = (const float*)d_in[12];
    const float* b1 = (const float*)d_in[13];
    const float* W2 = (const float*)d_in[14];
    const float* b2 = (const float*)d_in[15];
    const float* We = (const float*)d_in[16];
    const float* be = (const float*)d_in[17];
    const float* Wa = (const float*)d_in[18];
    const float* ba = (const float*)d_in[19];
    float* out = (float*)d_out;
    (void)in_sizes; (void)n_in; (void)out_size;

    int n4 = (int)(OUT_TOTAL / 4);

    init_kernel<<<(n4 + 255) / 256, 256>>>(out, n4);
    route_kernel<0><<<N_NODE  / 256, 256>>>(ni,  nw,  nullptr, N_NODE);
    route_kernel<1><<<N_EDGE  / 256, 256>>>(ein, ewn, n2e,     N_EDGE);
    route_kernel<2><<<N_ANGLE / 256, 256>>>(ain, awn, n2a,     N_ANGLE);
    wcvt_kernel<3><<<dim3((ADIM / 32) * (DO_ANGLE / 32), 8), dim3(32, 8)>>>(Wa);
    moe_gemm_mma<3><<<dim3(CAPA / 128, 8), 256>>>(x_a,  ba, out + OUT_ANGLE);
    wcvt_kernel<2><<<dim3((EINFO/ 32) * (DO_EDGE  / 32), 8), dim3(32, 8)>>>(We);
    moe_gemm_mma<2><<<dim3(CAPE / 128, 8), 512>>>(x_e,  be, out + OUT_EDGE);
    wcvt_kernel<1><<<dim3((NSYM / 32) * (DO_NODE  / 32), 8), dim3(32, 8)>>>(W2);
    moe_gemm_mma<1><<<dim3(CAPN / 64, 8), 256>>>(x_m2, b2, out + OUT_M2);
    wcvt_kernel<0><<<dim3((ND   / 32) * (DO_NODE  / 32), 8), dim3(32, 8)>>>(W1);
    moe_gemm_mma<0><<<dim3(CAPN / 64, 8), 256>>>(x_m1, b1, out + OUT_M1);
}

// round 15
// speedup vs baseline: 1.4906x; 1.0563x over previous
#include <cuda_runtime.h>
#include <cuda_fp16.h>
#include <math.h>
#include <stdint.h>

// ---------------------------------------------------------------------------
// MoE dispatch/combine via mma.sync HMMA (sm_100 target):
//   out[m] = sum_k w[m,k] * silu(x[m] @ W[e(m,k)] + b[e(m,k)])
// R15: tile widening (the twice-proven lever) applied to m2 (BM=128, 512t,
// acc=32) and angle (BM=256, 512t, acc=48). Edge stays at R14's 512t/BM=128;
// m1 unchanged. All per-thread acc <= 48 regs (established safe bound).
// ---------------------------------------------------------------------------

#define N_NODE   8192
#define N_EDGE   65536
#define N_ANGLE  131072
#define ND       128
#define NSYM     768
#define EINFO    320
#define ADIM     128
#define DO_NODE  128
#define DO_EDGE  192
#define DO_ANGLE 96

#define CAPN 4096
#define CAPE 32768
#define CAPA 65536

#define OUT_M1    ((size_t)0)
#define OUT_M2    ((size_t)N_NODE * ND)
#define OUT_EDGE  (OUT_M2 + (size_t)N_NODE * ND)
#define OUT_ANGLE (OUT_EDGE + (size_t)N_EDGE * DO_EDGE)
#define OUT_TOTAL (OUT_ANGLE + (size_t)N_ANGLE * DO_ANGLE)   // 27,262,976 floats

// ---------------- device scratch -------------------------------------------
__device__ int   g_cnt[24];
__device__ __align__(16) int   g_rows_node [8 * CAPN];
__device__ __align__(16) float g_w_node    [8 * CAPN];
__device__ __align__(16) int   g_rows_edge [8 * CAPE];
__device__ __align__(16) float g_w_edge    [8 * CAPE];
__device__ __align__(16) int   g_rows_angle[8 * CAPA];
__device__ __align__(16) float g_w_angle   [8 * CAPA];

// transposed weights: [E][DOUT][DIN] fp16 (K-major rows)
__device__ __align__(16) __half g_w1t[(size_t)8 * DO_NODE  * ND];
__device__ __align__(16) __half g_w2t[(size_t)8 * DO_NODE  * NSYM];
__device__ __align__(16) __half g_wet[(size_t)8 * DO_EDGE  * EINFO];
__device__ __align__(16) __half g_wat[(size_t)8 * DO_ANGLE * ADIM];

// ---------------- helpers ---------------------------------------------------
__device__ __forceinline__ uint32_t smem_u32(const void* p) {
    uint32_t a;
    asm("{ .reg .u64 t; cvta.to.shared.u64 t, %1; cvt.u32.u64 %0, t; }"
        : "=r"(a) : "l"(p));
    return a;
}

__device__ __forceinline__ uint32_t h2b(__half2 h) {
    return *reinterpret_cast<uint32_t*>(&h);
}

#define LDMATRIX_X4(r0, r1, r2, r3, addr) \
    asm volatile("ldmatrix.sync.aligned.m8n8.x4.shared.b16 {%0,%1,%2,%3}, [%4];" \
                 : "=r"(r0), "=r"(r1), "=r"(r2), "=r"(r3) : "r"(addr))

#define LDMATRIX_X2(r0, r1, addr) \
    asm volatile("ldmatrix.sync.aligned.m8n8.x2.shared.b16 {%0,%1}, [%2];" \
                 : "=r"(r0), "=r"(r1) : "r"(addr))

#define MMA_16816(c, a, b) \
    asm volatile("mma.sync.aligned.m16n8k16.row.col.f32.f16.f16.f32 " \
                 "{%0,%1,%2,%3}, {%4,%5,%6,%7}, {%8,%9}, {%0,%1,%2,%3};" \
                 : "+f"((c)[0]), "+f"((c)[1]), "+f"((c)[2]), "+f"((c)[3]) \
                 : "r"((a)[0]), "r"((a)[1]), "r"((a)[2]), "r"((a)[3]), \
                   "r"((b)[0]), "r"((b)[1]))

#define STS128(addr, v0, v1, v2, v3) \
    asm volatile("st.shared.v4.b32 [%0], {%1,%2,%3,%4};" \
                 :: "r"(addr), "r"(v0), "r"(v1), "r"(v2), "r"(v3) : "memory")

// ---------------- init: zero outputs + counters ------------------------------
__global__ void init_kernel(float* __restrict__ out, int n4) {
    int i = blockIdx.x * blockDim.x + threadIdx.x;
    if (i < n4) reinterpret_cast<float4*>(out)[i] = make_float4(0.f, 0.f, 0.f, 0.f);
    if (i < 24) g_cnt[i] = 0;
}

// ---------------- coalesced transpose+convert weights -----------------------
template<int WHICH>
__global__ void wcvt_kernel(const float* __restrict__ W) {
    constexpr int DIN  = (WHICH == 0) ? ND : (WHICH == 1) ? NSYM : (WHICH == 2) ? EINFO : ADIM;
    constexpr int DOUT = (WHICH <= 1) ? DO_NODE : (WHICH == 2) ? DO_EDGE : DO_ANGLE;
    __half* Wt;
    if      (WHICH == 0) Wt = g_w1t;
    else if (WHICH == 1) Wt = g_w2t;
    else if (WHICH == 2) Wt = g_wet;
    else                 Wt = g_wat;

    __shared__ float t[32][33];
    const int e  = blockIdx.y;
    const int nk = DIN / 32;
    const int k0 = (blockIdx.x % nk) * 32;
    const int n0 = (blockIdx.x / nk) * 32;
    const int tx = threadIdx.x, ty = threadIdx.y;
#pragma unroll
    for (int i = 0; i < 4; ++i)
        t[ty + 8 * i][tx] = W[((size_t)e * DIN + k0 + ty + 8 * i) * DOUT + n0 + tx];
    __syncthreads();
#pragma unroll
    for (int i = 0; i < 4; ++i)
        Wt[((size_t)e * DOUT + n0 + ty + 8 * i) * DIN + k0 + tx] =
            __float2half_rn(t[tx][ty + 8 * i]);
}

// ---------------- routing ---------------------------------------------------
template<int WHICH>
__global__ void route_kernel(const int* __restrict__ idx,
                             const float* __restrict__ wts,
                             const int* __restrict__ map, int M) {
    int* cnt = g_cnt + WHICH * 8;
    int* rowlist; float* wlist; int cap;
    if      (WHICH == 0) { rowlist = g_rows_node;  wlist = g_w_node;  cap = CAPN; }
    else if (WHICH == 1) { rowlist = g_rows_edge;  wlist = g_w_edge;  cap = CAPE; }
    else                 { rowlist = g_rows_angle; wlist = g_w_angle; cap = CAPA; }

    int i = blockIdx.x * blockDim.x + threadIdx.x;
    if (i >= M) return;
    int src = (WHICH == 0) ? i : map[i];
    int lane = threadIdx.x & 31;

#pragma unroll
    for (int k = 0; k < 2; ++k) {
        int   e = idx[2 * src + k];
        float w = wts[2 * src + k];
        unsigned mask = __match_any_sync(0xffffffffu, e);
        int leader = __ffs(mask) - 1;
        int rank   = __popc(mask & ((1u << lane) - 1u));
        int base = 0;
        if (lane == leader) base = atomicAdd(&cnt[e], __popc(mask));
        base = __shfl_sync(mask, base, leader);
        int p = base + rank;
        if (p > cap - 1) p = cap - 1;     // statistically impossible; keep in bounds
        int flat = e * cap + p;
        rowlist[flat] = i;
        wlist[flat]   = w;
    }
}

// ---------------- grouped HMMA GEMM -----------------------------------------
// BM rows x full DOUT per CTA, NT threads. Warp grid NWM x NWN covers
// (NWM*32) x DOUT. BK=32, K-major smem, 80B rows (conflict-free ldmatrix).
// A loaded fp32 (gathered once) and converted fp16 during the fill; register
// prefetch overlaps next chunk's LDGs with current MMAs. Epilogue: bias +
// silu + topk-weight, fp32 atomicAdd into pre-zeroed output.
// Configs (per-thread acc regs):
//   m1    256t  BM=64   2x4  WN=32 FN=4  acc=32
//   m2    512t  BM=128  4x4  WN=32 FN=4  acc=32
//   edge  512t  BM=128  4x4  WN=48 FN=6  acc=48
//   angle 512t  BM=256  8x2  WN=48 FN=6  acc=48
template<int WHICH>
__global__ void __launch_bounds__((WHICH == 0) ? 256 : 512)
moe_gemm_mma(const float* __restrict__ X, const float* __restrict__ Bias,
             float* __restrict__ Out) {
    constexpr int DIN  = (WHICH == 0) ? ND : (WHICH == 1) ? NSYM : (WHICH == 2) ? EINFO : ADIM;
    constexpr int DOUT = (WHICH <= 1) ? DO_NODE : (WHICH == 2) ? DO_EDGE : DO_ANGLE;
    constexpr int CAP  = (WHICH <= 1) ? CAPN : (WHICH == 2) ? CAPE : CAPA;
    constexpr int NT   = (WHICH == 0) ? 256 : 512;                 // threads
    constexpr int BM   = (WHICH == 0) ? 64 : (WHICH == 3) ? 256 : 128;  // tile rows
    constexpr int NWM  = BM / 32;                    // warps along M
    constexpr int NWN  = (NT / 32) / NWM;            // warps along N
    constexpr int WN   = DOUT / NWN;     // cols per warp band
    constexpr int FN   = WN / 8;         // n fragments per warp (<=6)
    constexpr int NCH  = DIN / 32;
    constexpr int TPR  = NT / BM;        // threads per A row (4 or 2)
    constexpr int F4   = 8 / TPR;        // float4 A loads per thread

    const __half* Wt;
    const int* rowlist; const float* wlist;
    if (WHICH == 0) { Wt = g_w1t; rowlist = g_rows_node;  wlist = g_w_node;  }
    if (WHICH == 1) { Wt = g_w2t; rowlist = g_rows_node;  wlist = g_w_node;  }
    if (WHICH == 2) { Wt = g_wet; rowlist = g_rows_edge;  wlist = g_w_edge;  }
    if (WHICH == 3) { Wt = g_wat; rowlist = g_rows_angle; wlist = g_w_angle; }
    const int which_r = (WHICH <= 1) ? 0 : (WHICH - 1);

    const int e = blockIdx.y;
    int count = min(g_cnt[which_r * 8 + e], CAP);
    const int m0 = blockIdx.x * BM;
    if (m0 >= count) return;

    __shared__ __align__(16) __half As[BM * 40];     // BM rows x 80B
    __shared__ __align__(16) __half Bs[DOUT * 40];   // DOUT rows x 80B
    __shared__ int   srow[BM];
    __shared__ float swt[BM];

    const int tid  = threadIdx.x;
    const int wid  = tid >> 5;
    const int lane = tid & 31;
    const int warp_m = wid % NWM;
    const int warp_n = wid / NWM;

    for (int t = tid; t < BM; t += NT) {
        int m = m0 + t;
        if (m < count) { srow[t] = rowlist[e * CAP + m]; swt[t] = wlist[e * CAP + m]; }
        else           { srow[t] = rowlist[e * CAP];     swt[t] = 0.f; }
    }
    __syncthreads();

    // A fill: TPR threads per row, F4 float4 loads each per 32-chunk
    const int arow = tid / TPR;
    const int aseg = tid % TPR;
    const float* aptr = X + (size_t)srow[arow] * DIN + aseg * (F4 * 4);
    const bool bval = tid < DOUT;
    const __half* bptr = Wt + ((size_t)e * DOUT + (bval ? tid : 0)) * DIN;

    const uint32_t As_u = smem_u32(As), Bs_u = smem_u32(Bs);
    const uint32_t a_st = As_u + (uint32_t)arow * 80u + (uint32_t)(aseg * F4 * 8);
    const uint32_t b_st = Bs_u + (uint32_t)tid * 80u;
    const uint32_t a_ld = As_u + (uint32_t)(warp_m * 32 + (lane & 15)) * 80u
                          + (uint32_t)(lane >> 4) * 16u;
    const uint32_t b_ld = Bs_u + (uint32_t)(warp_n * WN + (lane & 7)) * 80u
                          + (uint32_t)((lane >> 3) & 1) * 16u;

    float acc[2][FN][4];
#pragma unroll
    for (int i = 0; i < 2; ++i)
#pragma unroll
        for (int j = 0; j < FN; ++j)
#pragma unroll
            for (int q = 0; q < 4; ++q) acc[i][j][q] = 0.f;

    float4 ar[F4];
    uint4  br[4];

    // prologue prefetch (chunk 0)
#pragma unroll
    for (int j = 0; j < F4; ++j)
        ar[j] = *reinterpret_cast<const float4*>(aptr + j * 4);
    if (bval) {
#pragma unroll
        for (int j = 0; j < 4; ++j) br[j] = *reinterpret_cast<const uint4*>(bptr + j * 8);
    }

    for (int c = 0; c < NCH; ++c) {
        __syncthreads();    // previous chunk's ldmatrix reads complete
#pragma unroll
        for (int j = 0; j < F4; j += 2) {
            uint32_t u0 = h2b(__floats2half2_rn(ar[j].x,     ar[j].y));
            uint32_t u1 = h2b(__floats2half2_rn(ar[j].z,     ar[j].w));
            uint32_t u2 = h2b(__floats2half2_rn(ar[j + 1].x, ar[j + 1].y));
            uint32_t u3 = h2b(__floats2half2_rn(ar[j + 1].z, ar[j + 1].w));
            STS128(a_st + (uint32_t)(j / 2) * 16u, u0, u1, u2, u3);
        }
        if (bval) {
#pragma unroll
            for (int j = 0; j < 4; ++j)
                STS128(b_st + (uint32_t)j * 16u, br[j].x, br[j].y, br[j].z, br[j].w);
        }
        __syncthreads();
        // prefetch next chunk (LDG latency overlaps MMA below)
        if (c + 1 < NCH) {
#pragma unroll
            for (int j = 0; j < F4; ++j)
                ar[j] = *reinterpret_cast<const float4*>(aptr + (c + 1) * 32 + j * 4);
            if (bval) {
#pragma unroll
                for (int j = 0; j < 4; ++j)
                    br[j] = *reinterpret_cast<const uint4*>(bptr + (c + 1) * 32 + j * 8);
            }
        }
#pragma unroll
        for (int kk = 0; kk < 2; ++kk) {
            uint32_t a[2][4], b[FN][2];
#pragma unroll
            for (int fm = 0; fm < 2; ++fm)
                LDMATRIX_X4(a[fm][0], a[fm][1], a[fm][2], a[fm][3],
                            a_ld + (uint32_t)fm * 16u * 80u + (uint32_t)kk * 32u);
#pragma unroll
            for (int fn = 0; fn < FN; ++fn)
                LDMATRIX_X2(b[fn][0], b[fn][1],
                            b_ld + (uint32_t)fn * 8u * 80u + (uint32_t)kk * 32u);
#pragma unroll
            for (int fm = 0; fm < 2; ++fm)
#pragma unroll
                for (int fn = 0; fn < FN; ++fn)
                    MMA_16816(acc[fm][fn], a[fm], b[fn]);
        }
    }

    // epilogue: bias + silu + topk-weight -> fp32 atomicAdd into output
    const int qrow = lane >> 2;
    const int qcol = (lane & 3) * 2;
    const float* be = Bias + e * DOUT;
#pragma unroll
    for (int fm = 0; fm < 2; ++fm) {
#pragma unroll
        for (int hf = 0; hf < 2; ++hf) {
            int rloc = warp_m * 32 + fm * 16 + hf * 8 + qrow;
            int m = m0 + rloc;
            if (m >= count) continue;
            float wt = swt[rloc];
            float* orow = Out + (size_t)srow[rloc] * DOUT;
#pragma unroll
            for (int fn = 0; fn < FN; ++fn) {
                int col = warp_n * WN + fn * 8 + qcol;
                float h0 = acc[fm][fn][hf * 2 + 0] + be[col];
                float h1 = acc[fm][fn][hf * 2 + 1] + be[col + 1];
                atomicAdd(orow + col,     wt * (h0 / (1.f + __expf(-h0))));
                atomicAdd(orow + col + 1, wt * (h1 / (1.f + __expf(-h1))));
            }
        }
    }
}

// ---------------- launch ----------------------------------------------------
extern "C" void kernel_launch(void* const* d_in, const int* in_sizes, int n_in,
                              void* d_out, int out_size) {
    const float* x_m1 = (const float*)d_in[0];
    const float* x_m2 = (const float*)d_in[1];
    const float* x_e  = (const float*)d_in[2];
    const float* x_a  = (const float*)d_in[3];
    const float* nw   = (const float*)d_in[4];
    const int*   ni   = (const int*)  d_in[5];
    const float* ewn  = (const float*)d_in[6];
    const int*   ein  = (const int*)  d_in[7];
    const float* awn  = (const float*)d_in[8];
    const int*   ain  = (const int*)  d_in[9];
    const int*   n2e  = (const int*)  d_in[10];
    const int*   n2a  = (const int*)  d_in[11];
    const float* W1 = (const float*)d_in[12];
    const float* b1 = (const float*)d_in[13];
    const float* W2 = (const float*)d_in[14];
    const float* b2 = (const float*)d_in[15];
    const float* We = (const float*)d_in[16];
    const float* be = (const float*)d_in[17];
    const float* Wa = (const float*)d_in[18];
    const float* ba = (const float*)d_in[19];
    float* out = (float*)d_out;
    (void)in_sizes; (void)n_in; (void)out_size;

    int n4 = (int)(OUT_TOTAL / 4);

    init_kernel<<<(n4 + 255) / 256, 256>>>(out, n4);
    route_kernel<0><<<N_NODE  / 256, 256>>>(ni,  nw,  nullptr, N_NODE);
    route_kernel<1><<<N_EDGE  / 256, 256>>>(ein, ewn, n2e,     N_EDGE);
    route_kernel<2><<<N_ANGLE / 256, 256>>>(ain, awn, n2a,     N_ANGLE);
    wcvt_kernel<3><<<dim3((ADIM / 32) * (DO_ANGLE / 32), 8), dim3(32, 8)>>>(Wa);
    moe_gemm_mma<3><<<dim3(CAPA / 256, 8), 512>>>(x_a,  ba, out + OUT_ANGLE);
    wcvt_kernel<2><<<dim3((EINFO/ 32) * (DO_EDGE  / 32), 8), dim3(32, 8)>>>(We);
    moe_gemm_mma<2><<<dim3(CAPE / 128, 8), 512>>>(x_e,  be, out + OUT_EDGE);
    wcvt_kernel<1><<<dim3((NSYM / 32) * (DO_NODE  / 32), 8), dim3(32, 8)>>>(W2);
    moe_gemm_mma<1><<<dim3(CAPN / 128, 8), 512>>>(x_m2, b2, out + OUT_M2);
    wcvt_kernel<0><<<dim3((ND   / 32) * (DO_NODE  / 32), 8), dim3(32, 8)>>>(W1);
    moe_gemm_mma<0><<<dim3(CAPN / 64, 8), 256>>>(x_m1, b1, out + OUT_M1);
}

// round 16
// speedup vs baseline: 1.5591x; 1.0459x over previous
#include <cuda_runtime.h>
#include <cuda_fp16.h>
#include <math.h>
#include <stdint.h>

// ---------------------------------------------------------------------------
// MoE dispatch/combine via mma.sync HMMA (sm_100 target):
//   out[m] = sum_k w[m,k] * silu(x[m] @ W[e(m,k)] + b[e(m,k)])
// R16: BK widened 32->64 for m1/m2/edge (halves chunk-iterations / barriers;
// B fill spread over 2 threads/row to keep prefetch regs flat). Angle stays
// BK=32 (smem limit at BM=256). Tile shapes otherwise = R15 champion.
// ---------------------------------------------------------------------------

#define N_NODE   8192
#define N_EDGE   65536
#define N_ANGLE  131072
#define ND       128
#define NSYM     768
#define EINFO    320
#define ADIM     128
#define DO_NODE  128
#define DO_EDGE  192
#define DO_ANGLE 96

#define CAPN 4096
#define CAPE 32768
#define CAPA 65536

#define OUT_M1    ((size_t)0)
#define OUT_M2    ((size_t)N_NODE * ND)
#define OUT_EDGE  (OUT_M2 + (size_t)N_NODE * ND)
#define OUT_ANGLE (OUT_EDGE + (size_t)N_EDGE * DO_EDGE)
#define OUT_TOTAL (OUT_ANGLE + (size_t)N_ANGLE * DO_ANGLE)   // 27,262,976 floats

// ---------------- device scratch -------------------------------------------
__device__ int   g_cnt[24];
__device__ __align__(16) int   g_rows_node [8 * CAPN];
__device__ __align__(16) float g_w_node    [8 * CAPN];
__device__ __align__(16) int   g_rows_edge [8 * CAPE];
__device__ __align__(16) float g_w_edge    [8 * CAPE];
__device__ __align__(16) int   g_rows_angle[8 * CAPA];
__device__ __align__(16) float g_w_angle   [8 * CAPA];

// transposed weights: [E][DOUT][DIN] fp16 (K-major rows)
__device__ __align__(16) __half g_w1t[(size_t)8 * DO_NODE  * ND];
__device__ __align__(16) __half g_w2t[(size_t)8 * DO_NODE  * NSYM];
__device__ __align__(16) __half g_wet[(size_t)8 * DO_EDGE  * EINFO];
__device__ __align__(16) __half g_wat[(size_t)8 * DO_ANGLE * ADIM];

// ---------------- helpers ---------------------------------------------------
__device__ __forceinline__ uint32_t smem_u32(const void* p) {
    uint32_t a;
    asm("{ .reg .u64 t; cvta.to.shared.u64 t, %1; cvt.u32.u64 %0, t; }"
        : "=r"(a) : "l"(p));
    return a;
}

__device__ __forceinline__ uint32_t h2b(__half2 h) {
    return *reinterpret_cast<uint32_t*>(&h);
}

#define LDMATRIX_X4(r0, r1, r2, r3, addr) \
    asm volatile("ldmatrix.sync.aligned.m8n8.x4.shared.b16 {%0,%1,%2,%3}, [%4];" \
                 : "=r"(r0), "=r"(r1), "=r"(r2), "=r"(r3) : "r"(addr))

#define LDMATRIX_X2(r0, r1, addr) \
    asm volatile("ldmatrix.sync.aligned.m8n8.x2.shared.b16 {%0,%1}, [%2];" \
                 : "=r"(r0), "=r"(r1) : "r"(addr))

#define MMA_16816(c, a, b) \
    asm volatile("mma.sync.aligned.m16n8k16.row.col.f32.f16.f16.f32 " \
                 "{%0,%1,%2,%3}, {%4,%5,%6,%7}, {%8,%9}, {%0,%1,%2,%3};" \
                 : "+f"((c)[0]), "+f"((c)[1]), "+f"((c)[2]), "+f"((c)[3]) \
                 : "r"((a)[0]), "r"((a)[1]), "r"((a)[2]), "r"((a)[3]), \
                   "r"((b)[0]), "r"((b)[1]))

#define STS128(addr, v0, v1, v2, v3) \
    asm volatile("st.shared.v4.b32 [%0], {%1,%2,%3,%4};" \
                 :: "r"(addr), "r"(v0), "r"(v1), "r"(v2), "r"(v3) : "memory")

// ---------------- init: zero outputs + counters ------------------------------
__global__ void init_kernel(float* __restrict__ out, int n4) {
    int i = blockIdx.x * blockDim.x + threadIdx.x;
    if (i < n4) reinterpret_cast<float4*>(out)[i] = make_float4(0.f, 0.f, 0.f, 0.f);
    if (i < 24) g_cnt[i] = 0;
}

// ---------------- coalesced transpose+convert weights -----------------------
template<int WHICH>
__global__ void wcvt_kernel(const float* __restrict__ W) {
    constexpr int DIN  = (WHICH == 0) ? ND : (WHICH == 1) ? NSYM : (WHICH == 2) ? EINFO : ADIM;
    constexpr int DOUT = (WHICH <= 1) ? DO_NODE : (WHICH == 2) ? DO_EDGE : DO_ANGLE;
    __half* Wt;
    if      (WHICH == 0) Wt = g_w1t;
    else if (WHICH == 1) Wt = g_w2t;
    else if (WHICH == 2) Wt = g_wet;
    else                 Wt = g_wat;

    __shared__ float t[32][33];
    const int e  = blockIdx.y;
    const int nk = DIN / 32;
    const int k0 = (blockIdx.x % nk) * 32;
    const int n0 = (blockIdx.x / nk) * 32;
    const int tx = threadIdx.x, ty = threadIdx.y;
#pragma unroll
    for (int i = 0; i < 4; ++i)
        t[ty + 8 * i][tx] = W[((size_t)e * DIN + k0 + ty + 8 * i) * DOUT + n0 + tx];
    __syncthreads();
#pragma unroll
    for (int i = 0; i < 4; ++i)
        Wt[((size_t)e * DOUT + n0 + ty + 8 * i) * DIN + k0 + tx] =
            __float2half_rn(t[tx][ty + 8 * i]);
}

// ---------------- routing ---------------------------------------------------
template<int WHICH>
__global__ void route_kernel(const int* __restrict__ idx,
                             const float* __restrict__ wts,
                             const int* __restrict__ map, int M) {
    int* cnt = g_cnt + WHICH * 8;
    int* rowlist; float* wlist; int cap;
    if      (WHICH == 0) { rowlist = g_rows_node;  wlist = g_w_node;  cap = CAPN; }
    else if (WHICH == 1) { rowlist = g_rows_edge;  wlist = g_w_edge;  cap = CAPE; }
    else                 { rowlist = g_rows_angle; wlist = g_w_angle; cap = CAPA; }

    int i = blockIdx.x * blockDim.x + threadIdx.x;
    if (i >= M) return;
    int src = (WHICH == 0) ? i : map[i];
    int lane = threadIdx.x & 31;

#pragma unroll
    for (int k = 0; k < 2; ++k) {
        int   e = idx[2 * src + k];
        float w = wts[2 * src + k];
        unsigned mask = __match_any_sync(0xffffffffu, e);
        int leader = __ffs(mask) - 1;
        int rank   = __popc(mask & ((1u << lane) - 1u));
        int base = 0;
        if (lane == leader) base = atomicAdd(&cnt[e], __popc(mask));
        base = __shfl_sync(mask, base, leader);
        int p = base + rank;
        if (p > cap - 1) p = cap - 1;     // statistically impossible; keep in bounds
        int flat = e * cap + p;
        rowlist[flat] = i;
        wlist[flat]   = w;
    }
}

// ---------------- grouped HMMA GEMM -----------------------------------------
// BM rows x full DOUT per CTA, NT threads, BK-chunked K. Row stride in smem
// = BK+8 halves (80B or 144B; odd multiple of 16B -> conflict-free ldmatrix
// and STS128 phases). A loaded fp32 (gathered once) and converted fp16 during
// the fill; register prefetch overlaps next chunk's LDGs with current MMAs.
// B fill spread over TPB=BK/32 threads per row (prefetch regs flat in BK).
// Epilogue: bias + silu + topk-weight, fp32 atomicAdd into pre-zeroed output.
// Configs:
//   m1    256t  BM=64   BK=64  2x4  FN=4  acc=32
//   m2    512t  BM=128  BK=64  4x4  FN=4  acc=32
//   edge  512t  BM=128  BK=64  4x4  FN=6  acc=48
//   angle 512t  BM=256  BK=32  8x2  FN=6  acc=48
template<int WHICH>
__global__ void __launch_bounds__((WHICH == 0) ? 256 : 512)
moe_gemm_mma(const float* __restrict__ X, const float* __restrict__ Bias,
             float* __restrict__ Out) {
    constexpr int DIN  = (WHICH == 0) ? ND : (WHICH == 1) ? NSYM : (WHICH == 2) ? EINFO : ADIM;
    constexpr int DOUT = (WHICH <= 1) ? DO_NODE : (WHICH == 2) ? DO_EDGE : DO_ANGLE;
    constexpr int CAP  = (WHICH <= 1) ? CAPN : (WHICH == 2) ? CAPE : CAPA;
    constexpr int NT   = (WHICH == 0) ? 256 : 512;                 // threads
    constexpr int BM   = (WHICH == 0) ? 64 : (WHICH == 3) ? 256 : 128;  // tile rows
    constexpr int BK   = (WHICH == 3) ? 32 : 64;     // K per chunk
    constexpr int RS   = BK + 8;         // smem row stride (halves)
    constexpr int NWM  = BM / 32;                    // warps along M
    constexpr int NWN  = (NT / 32) / NWM;            // warps along N
    constexpr int WN   = DOUT / NWN;     // cols per warp band
    constexpr int FN   = WN / 8;         // n fragments per warp (<=6)
    constexpr int NCH  = DIN / BK;
    constexpr int KST  = BK / 16;        // K=16 MMA steps per chunk
    constexpr int TPR  = NT / BM;        // threads per A row (4 or 2)
    constexpr int FLT  = BK / TPR;       // fp32 per thread per chunk (16 or 8)
    constexpr int F4   = FLT / 4;        // float4 A loads per thread
    constexpr int TPB  = BK / 32;        // threads per B row (1 or 2)

    const __half* Wt;
    const int* rowlist; const float* wlist;
    if (WHICH == 0) { Wt = g_w1t; rowlist = g_rows_node;  wlist = g_w_node;  }
    if (WHICH == 1) { Wt = g_w2t; rowlist = g_rows_node;  wlist = g_w_node;  }
    if (WHICH == 2) { Wt = g_wet; rowlist = g_rows_edge;  wlist = g_w_edge;  }
    if (WHICH == 3) { Wt = g_wat; rowlist = g_rows_angle; wlist = g_w_angle; }
    const int which_r = (WHICH <= 1) ? 0 : (WHICH - 1);

    const int e = blockIdx.y;
    int count = min(g_cnt[which_r * 8 + e], CAP);
    const int m0 = blockIdx.x * BM;
    if (m0 >= count) return;

    __shared__ __align__(16) __half As[BM * RS];     // BM rows x (2*RS)B
    __shared__ __align__(16) __half Bs[DOUT * RS];   // DOUT rows x (2*RS)B
    __shared__ int   srow[BM];
    __shared__ float swt[BM];

    const int tid  = threadIdx.x;
    const int wid  = tid >> 5;
    const int lane = tid & 31;
    const int warp_m = wid % NWM;
    const int warp_n = wid / NWM;

    for (int t = tid; t < BM; t += NT) {
        int m = m0 + t;
        if (m < count) { srow[t] = rowlist[e * CAP + m]; swt[t] = wlist[e * CAP + m]; }
        else           { srow[t] = rowlist[e * CAP];     swt[t] = 0.f; }
    }
    __syncthreads();

    // A fill: TPR threads per row, FLT fp32 each per chunk
    const int arow = tid / TPR;
    const int aseg = tid % TPR;
    const float* aptr = X + (size_t)srow[arow] * DIN + aseg * FLT;
    // B fill: TPB threads per row, 32 halves (4x16B) each
    const int brow  = tid / TPB;
    const int bhalf = tid % TPB;
    const bool bval = brow < DOUT;
    const __half* bptr = Wt + ((size_t)e * DOUT + (bval ? brow : 0)) * DIN + bhalf * 32;

    const uint32_t As_u = smem_u32(As), Bs_u = smem_u32(Bs);
    const uint32_t a_st = As_u + (uint32_t)arow * (RS * 2) + (uint32_t)(aseg * FLT * 2);
    const uint32_t b_st = Bs_u + (uint32_t)brow * (RS * 2) + (uint32_t)bhalf * 64u;
    const uint32_t a_ld = As_u + (uint32_t)(warp_m * 32 + (lane & 15)) * (RS * 2)
                          + (uint32_t)(lane >> 4) * 16u;
    const uint32_t b_ld = Bs_u + (uint32_t)(warp_n * WN + (lane & 7)) * (RS * 2)
                          + (uint32_t)((lane >> 3) & 1) * 16u;

    float acc[2][FN][4];
#pragma unroll
    for (int i = 0; i < 2; ++i)
#pragma unroll
        for (int j = 0; j < FN; ++j)
#pragma unroll
            for (int q = 0; q < 4; ++q) acc[i][j][q] = 0.f;

    float4 ar[F4];
    uint4  br[4];

    // prologue prefetch (chunk 0)
#pragma unroll
    for (int j = 0; j < F4; ++j)
        ar[j] = *reinterpret_cast<const float4*>(aptr + j * 4);
    if (bval) {
#pragma unroll
        for (int j = 0; j < 4; ++j) br[j] = *reinterpret_cast<const uint4*>(bptr + j * 8);
    }

    for (int c = 0; c < NCH; ++c) {
        __syncthreads();    // previous chunk's ldmatrix reads complete
#pragma unroll
        for (int j = 0; j < F4; j += 2) {
            uint32_t u0 = h2b(__floats2half2_rn(ar[j].x,     ar[j].y));
            uint32_t u1 = h2b(__floats2half2_rn(ar[j].z,     ar[j].w));
            uint32_t u2 = h2b(__floats2half2_rn(ar[j + 1].x, ar[j + 1].y));
            uint32_t u3 = h2b(__floats2half2_rn(ar[j + 1].z, ar[j + 1].w));
            STS128(a_st + (uint32_t)(j / 2) * 16u, u0, u1, u2, u3);
        }
        if (bval) {
#pragma unroll
            for (int j = 0; j < 4; ++j)
                STS128(b_st + (uint32_t)j * 16u, br[j].x, br[j].y, br[j].z, br[j].w);
        }
        __syncthreads();
        // prefetch next chunk (LDG latency overlaps MMA below)
        if (c + 1 < NCH) {
#pragma unroll
            for (int j = 0; j < F4; ++j)
                ar[j] = *reinterpret_cast<const float4*>(aptr + (c + 1) * BK + j * 4);
            if (bval) {
#pragma unroll
                for (int j = 0; j < 4; ++j)
                    br[j] = *reinterpret_cast<const uint4*>(bptr + (c + 1) * BK + j * 8);
            }
        }
#pragma unroll
        for (int kk = 0; kk < KST; ++kk) {
            uint32_t a[2][4], b[FN][2];
#pragma unroll
            for (int fm = 0; fm < 2; ++fm)
                LDMATRIX_X4(a[fm][0], a[fm][1], a[fm][2], a[fm][3],
                            a_ld + (uint32_t)fm * 16u * (RS * 2) + (uint32_t)kk * 32u);
#pragma unroll
            for (int fn = 0; fn < FN; ++fn)
                LDMATRIX_X2(b[fn][0], b[fn][1],
                            b_ld + (uint32_t)fn * 8u * (RS * 2) + (uint32_t)kk * 32u);
#pragma unroll
            for (int fm = 0; fm < 2; ++fm)
#pragma unroll
                for (int fn = 0; fn < FN; ++fn)
                    MMA_16816(acc[fm][fn], a[fm], b[fn]);
        }
    }

    // epilogue: bias + silu + topk-weight -> fp32 atomicAdd into output
    const int qrow = lane >> 2;
    const int qcol = (lane & 3) * 2;
    const float* be = Bias + e * DOUT;
#pragma unroll
    for (int fm = 0; fm < 2; ++fm) {
#pragma unroll
        for (int hf = 0; hf < 2; ++hf) {
            int rloc = warp_m * 32 + fm * 16 + hf * 8 + qrow;
            int m = m0 + rloc;
            if (m >= count) continue;
            float wt = swt[rloc];
            float* orow = Out + (size_t)srow[rloc] * DOUT;
#pragma unroll
            for (int fn = 0; fn < FN; ++fn) {
                int col = warp_n * WN + fn * 8 + qcol;
                float h0 = acc[fm][fn][hf * 2 + 0] + be[col];
                float h1 = acc[fm][fn][hf * 2 + 1] + be[col + 1];
                atomicAdd(orow + col,     wt * (h0 / (1.f + __expf(-h0))));
                atomicAdd(orow + col + 1, wt * (h1 / (1.f + __expf(-h1))));
            }
        }
    }
}

// ---------------- launch ----------------------------------------------------
extern "C" void kernel_launch(void* const* d_in, const int* in_sizes, int n_in,
                              void* d_out, int out_size) {
    const float* x_m1 = (const float*)d_in[0];
    const float* x_m2 = (const float*)d_in[1];
    const float* x_e  = (const float*)d_in[2];
    const float* x_a  = (const float*)d_in[3];
    const float* nw   = (const float*)d_in[4];
    const int*   ni   = (const int*)  d_in[5];
    const float* ewn  = (const float*)d_in[6];
    const int*   ein  = (const int*)  d_in[7];
    const float* awn  = (const float*)d_in[8];
    const int*   ain  = (const int*)  d_in[9];
    const int*   n2e  = (const int*)  d_in[10];
    const int*   n2a  = (const int*)  d_in[11];
    const float* W1 = (const float*)d_in[12];
    const float* b1 = (const float*)d_in[13];
    const float* W2 = (const float*)d_in[14];
    const float* b2 = (const float*)d_in[15];
    const float* We = (const float*)d_in[16];
    const float* be = (const float*)d_in[17];
    const float* Wa = (const float*)d_in[18];
    const float* ba = (const float*)d_in[19];
    float* out = (float*)d_out;
    (void)in_sizes; (void)n_in; (void)out_size;

    int n4 = (int)(OUT_TOTAL / 4);

    init_kernel<<<(n4 + 255) / 256, 256>>>(out, n4);
    route_kernel<0><<<N_NODE  / 256, 256>>>(ni,  nw,  nullptr, N_NODE);
    route_kernel<1><<<N_EDGE  / 256, 256>>>(ein, ewn, n2e,     N_EDGE);
    route_kernel<2><<<N_ANGLE / 256, 256>>>(ain, awn, n2a,     N_ANGLE);
    wcvt_kernel<3><<<dim3((ADIM / 32) * (DO_ANGLE / 32), 8), dim3(32, 8)>>>(Wa);
    moe_gemm_mma<3><<<dim3(CAPA / 256, 8), 512>>>(x_a,  ba, out + OUT_ANGLE);
    wcvt_kernel<2><<<dim3((EINFO/ 32) * (DO_EDGE  / 32), 8), dim3(32, 8)>>>(We);
    moe_gemm_mma<2><<<dim3(CAPE / 128, 8), 512>>>(x_e,  be, out + OUT_EDGE);
    wcvt_kernel<1><<<dim3((NSYM / 32) * (DO_NODE  / 32), 8), dim3(32, 8)>>>(W2);
    moe_gemm_mma<1><<<dim3(CAPN / 128, 8), 512>>>(x_m2, b2, out + OUT_M2);
    wcvt_kernel<0><<<dim3((ND   / 32) * (DO_NODE  / 32), 8), dim3(32, 8)>>>(W1);
    moe_gemm_mma<0><<<dim3(CAPN / 64, 8), 256>>>(x_m1, b1, out + OUT_M1);
}

// round 17
// speedup vs baseline: 1.5901x; 1.0199x over previous
#include <cuda_runtime.h>
#include <cuda_fp16.h>
#include <math.h>
#include <stdint.h>

// ---------------------------------------------------------------------------
// MoE dispatch/combine via mma.sync HMMA (sm_100 target):
//   out[m] = sum_k w[m,k] * silu(x[m] @ W[e(m,k)] + b[e(m,k)])
// R17: epilogue uses vectorized no-return reductions (red.global.add.v2.f32,
// halves atomic op count, removes the ATOMG return trip) and m1 joins the
// standard 512t/BM=128/BK=64 tile shape. Mainloop = R16 champion.
// ---------------------------------------------------------------------------

#define N_NODE   8192
#define N_EDGE   65536
#define N_ANGLE  131072
#define ND       128
#define NSYM     768
#define EINFO    320
#define ADIM     128
#define DO_NODE  128
#define DO_EDGE  192
#define DO_ANGLE 96

#define CAPN 4096
#define CAPE 32768
#define CAPA 65536

#define OUT_M1    ((size_t)0)
#define OUT_M2    ((size_t)N_NODE * ND)
#define OUT_EDGE  (OUT_M2 + (size_t)N_NODE * ND)
#define OUT_ANGLE (OUT_EDGE + (size_t)N_EDGE * DO_EDGE)
#define OUT_TOTAL (OUT_ANGLE + (size_t)N_ANGLE * DO_ANGLE)   // 27,262,976 floats

// ---------------- device scratch -------------------------------------------
__device__ int   g_cnt[24];
__device__ __align__(16) int   g_rows_node [8 * CAPN];
__device__ __align__(16) float g_w_node    [8 * CAPN];
__device__ __align__(16) int   g_rows_edge [8 * CAPE];
__device__ __align__(16) float g_w_edge    [8 * CAPE];
__device__ __align__(16) int   g_rows_angle[8 * CAPA];
__device__ __align__(16) float g_w_angle   [8 * CAPA];

// transposed weights: [E][DOUT][DIN] fp16 (K-major rows)
__device__ __align__(16) __half g_w1t[(size_t)8 * DO_NODE  * ND];
__device__ __align__(16) __half g_w2t[(size_t)8 * DO_NODE  * NSYM];
__device__ __align__(16) __half g_wet[(size_t)8 * DO_EDGE  * EINFO];
__device__ __align__(16) __half g_wat[(size_t)8 * DO_ANGLE * ADIM];

// ---------------- helpers ---------------------------------------------------
__device__ __forceinline__ uint32_t smem_u32(const void* p) {
    uint32_t a;
    asm("{ .reg .u64 t; cvta.to.shared.u64 t, %1; cvt.u32.u64 %0, t; }"
        : "=r"(a) : "l"(p));
    return a;
}

__device__ __forceinline__ uint32_t h2b(__half2 h) {
    return *reinterpret_cast<uint32_t*>(&h);
}

#define LDMATRIX_X4(r0, r1, r2, r3, addr) \
    asm volatile("ldmatrix.sync.aligned.m8n8.x4.shared.b16 {%0,%1,%2,%3}, [%4];" \
                 : "=r"(r0), "=r"(r1), "=r"(r2), "=r"(r3) : "r"(addr))

#define LDMATRIX_X2(r0, r1, addr) \
    asm volatile("ldmatrix.sync.aligned.m8n8.x2.shared.b16 {%0,%1}, [%2];" \
                 : "=r"(r0), "=r"(r1) : "r"(addr))

#define MMA_16816(c, a, b) \
    asm volatile("mma.sync.aligned.m16n8k16.row.col.f32.f16.f16.f32 " \
                 "{%0,%1,%2,%3}, {%4,%5,%6,%7}, {%8,%9}, {%0,%1,%2,%3};" \
                 : "+f"((c)[0]), "+f"((c)[1]), "+f"((c)[2]), "+f"((c)[3]) \
                 : "r"((a)[0]), "r"((a)[1]), "r"((a)[2]), "r"((a)[3]), \
                   "r"((b)[0]), "r"((b)[1]))

#define STS128(addr, v0, v1, v2, v3) \
    asm volatile("st.shared.v4.b32 [%0], {%1,%2,%3,%4};" \
                 :: "r"(addr), "r"(v0), "r"(v1), "r"(v2), "r"(v3) : "memory")

// vectorized no-return fp32 reduction (PTX ISA 8.x, sm_90+)
#define RED2_F32(addr, v0, v1) \
    asm volatile("red.global.add.v2.f32 [%0], {%1, %2};" \
                 :: "l"(addr), "f"(v0), "f"(v1) : "memory")

// ---------------- init: zero outputs + counters ------------------------------
__global__ void init_kernel(float* __restrict__ out, int n4) {
    int i = blockIdx.x * blockDim.x + threadIdx.x;
    if (i < n4) reinterpret_cast<float4*>(out)[i] = make_float4(0.f, 0.f, 0.f, 0.f);
    if (i < 24) g_cnt[i] = 0;
}

// ---------------- coalesced transpose+convert weights -----------------------
template<int WHICH>
__global__ void wcvt_kernel(const float* __restrict__ W) {
    constexpr int DIN  = (WHICH == 0) ? ND : (WHICH == 1) ? NSYM : (WHICH == 2) ? EINFO : ADIM;
    constexpr int DOUT = (WHICH <= 1) ? DO_NODE : (WHICH == 2) ? DO_EDGE : DO_ANGLE;
    __half* Wt;
    if      (WHICH == 0) Wt = g_w1t;
    else if (WHICH == 1) Wt = g_w2t;
    else if (WHICH == 2) Wt = g_wet;
    else                 Wt = g_wat;

    __shared__ float t[32][33];
    const int e  = blockIdx.y;
    const int nk = DIN / 32;
    const int k0 = (blockIdx.x % nk) * 32;
    const int n0 = (blockIdx.x / nk) * 32;
    const int tx = threadIdx.x, ty = threadIdx.y;
#pragma unroll
    for (int i = 0; i < 4; ++i)
        t[ty + 8 * i][tx] = W[((size_t)e * DIN + k0 + ty + 8 * i) * DOUT + n0 + tx];
    __syncthreads();
#pragma unroll
    for (int i = 0; i < 4; ++i)
        Wt[((size_t)e * DOUT + n0 + ty + 8 * i) * DIN + k0 + tx] =
            __float2half_rn(t[tx][ty + 8 * i]);
}

// ---------------- routing ---------------------------------------------------
template<int WHICH>
__global__ void route_kernel(const int* __restrict__ idx,
                             const float* __restrict__ wts,
                             const int* __restrict__ map, int M) {
    int* cnt = g_cnt + WHICH * 8;
    int* rowlist; float* wlist; int cap;
    if      (WHICH == 0) { rowlist = g_rows_node;  wlist = g_w_node;  cap = CAPN; }
    else if (WHICH == 1) { rowlist = g_rows_edge;  wlist = g_w_edge;  cap = CAPE; }
    else                 { rowlist = g_rows_angle; wlist = g_w_angle; cap = CAPA; }

    int i = blockIdx.x * blockDim.x + threadIdx.x;
    if (i >= M) return;
    int src = (WHICH == 0) ? i : map[i];
    int lane = threadIdx.x & 31;

#pragma unroll
    for (int k = 0; k < 2; ++k) {
        int   e = idx[2 * src + k];
        float w = wts[2 * src + k];
        unsigned mask = __match_any_sync(0xffffffffu, e);
        int leader = __ffs(mask) - 1;
        int rank   = __popc(mask & ((1u << lane) - 1u));
        int base = 0;
        if (lane == leader) base = atomicAdd(&cnt[e], __popc(mask));
        base = __shfl_sync(mask, base, leader);
        int p = base + rank;
        if (p > cap - 1) p = cap - 1;     // statistically impossible; keep in bounds
        int flat = e * cap + p;
        rowlist[flat] = i;
        wlist[flat]   = w;
    }
}

// ---------------- grouped HMMA GEMM -----------------------------------------
// BM rows x full DOUT per CTA, 512 threads, BK-chunked K. Smem row stride
// = BK+8 halves (conflict-free ldmatrix + STS128). A loaded fp32 (gathered
// once) and converted fp16 during the fill; register prefetch overlaps next
// chunk's LDGs with current MMAs. B fill spread over BK/32 threads per row.
// Epilogue: bias + silu + topk-weight -> red.global.add.v2.f32 (no-return).
// Configs:
//   m1    BM=128 BK=64  4x4  FN=4  acc=32
//   m2    BM=128 BK=64  4x4  FN=4  acc=32
//   edge  BM=128 BK=64  4x4  FN=6  acc=48
//   angle BM=256 BK=32  8x2  FN=6  acc=48
template<int WHICH>
__global__ void __launch_bounds__(512)
moe_gemm_mma(const float* __restrict__ X, const float* __restrict__ Bias,
             float* __restrict__ Out) {
    constexpr int DIN  = (WHICH == 0) ? ND : (WHICH == 1) ? NSYM : (WHICH == 2) ? EINFO : ADIM;
    constexpr int DOUT = (WHICH <= 1) ? DO_NODE : (WHICH == 2) ? DO_EDGE : DO_ANGLE;
    constexpr int CAP  = (WHICH <= 1) ? CAPN : (WHICH == 2) ? CAPE : CAPA;
    constexpr int NT   = 512;
    constexpr int BM   = (WHICH == 3) ? 256 : 128;   // tile rows
    constexpr int BK   = (WHICH == 3) ? 32 : 64;     // K per chunk
    constexpr int RS   = BK + 8;         // smem row stride (halves)
    constexpr int NWM  = BM / 32;                    // warps along M
    constexpr int NWN  = (NT / 32) / NWM;            // warps along N
    constexpr int WN   = DOUT / NWN;     // cols per warp band
    constexpr int FN   = WN / 8;         // n fragments per warp (<=6)
    constexpr int NCH  = DIN / BK;
    constexpr int KST  = BK / 16;        // K=16 MMA steps per chunk
    constexpr int TPR  = NT / BM;        // threads per A row (4 or 2)
    constexpr int FLT  = BK / TPR;       // fp32 per thread per chunk (16)
    constexpr int F4   = FLT / 4;        // float4 A loads per thread
    constexpr int TPB  = BK / 32;        // threads per B row (1 or 2)

    const __half* Wt;
    const int* rowlist; const float* wlist;
    if (WHICH == 0) { Wt = g_w1t; rowlist = g_rows_node;  wlist = g_w_node;  }
    if (WHICH == 1) { Wt = g_w2t; rowlist = g_rows_node;  wlist = g_w_node;  }
    if (WHICH == 2) { Wt = g_wet; rowlist = g_rows_edge;  wlist = g_w_edge;  }
    if (WHICH == 3) { Wt = g_wat; rowlist = g_rows_angle; wlist = g_w_angle; }
    const int which_r = (WHICH <= 1) ? 0 : (WHICH - 1);

    const int e = blockIdx.y;
    int count = min(g_cnt[which_r * 8 + e], CAP);
    const int m0 = blockIdx.x * BM;
    if (m0 >= count) return;

    __shared__ __align__(16) __half As[BM * RS];     // BM rows x (2*RS)B
    __shared__ __align__(16) __half Bs[DOUT * RS];   // DOUT rows x (2*RS)B
    __shared__ int   srow[BM];
    __shared__ float swt[BM];

    const int tid  = threadIdx.x;
    const int wid  = tid >> 5;
    const int lane = tid & 31;
    const int warp_m = wid % NWM;
    const int warp_n = wid / NWM;

    for (int t = tid; t < BM; t += NT) {
        int m = m0 + t;
        if (m < count) { srow[t] = rowlist[e * CAP + m]; swt[t] = wlist[e * CAP + m]; }
        else           { srow[t] = rowlist[e * CAP];     swt[t] = 0.f; }
    }
    __syncthreads();

    // A fill: TPR threads per row, FLT fp32 each per chunk
    const int arow = tid / TPR;
    const int aseg = tid % TPR;
    const float* aptr = X + (size_t)srow[arow] * DIN + aseg * FLT;
    // B fill: TPB threads per row, 32 halves (4x16B) each
    const int brow  = tid / TPB;
    const int bhalf = tid % TPB;
    const bool bval = brow < DOUT;
    const __half* bptr = Wt + ((size_t)e * DOUT + (bval ? brow : 0)) * DIN + bhalf * 32;

    const uint32_t As_u = smem_u32(As), Bs_u = smem_u32(Bs);
    const uint32_t a_st = As_u + (uint32_t)arow * (RS * 2) + (uint32_t)(aseg * FLT * 2);
    const uint32_t b_st = Bs_u + (uint32_t)brow * (RS * 2) + (uint32_t)bhalf * 64u;
    const uint32_t a_ld = As_u + (uint32_t)(warp_m * 32 + (lane & 15)) * (RS * 2)
                          + (uint32_t)(lane >> 4) * 16u;
    const uint32_t b_ld = Bs_u + (uint32_t)(warp_n * WN + (lane & 7)) * (RS * 2)
                          + (uint32_t)((lane >> 3) & 1) * 16u;

    float acc[2][FN][4];
#pragma unroll
    for (int i = 0; i < 2; ++i)
#pragma unroll
        for (int j = 0; j < FN; ++j)
#pragma unroll
            for (int q = 0; q < 4; ++q) acc[i][j][q] = 0.f;

    float4 ar[F4];
    uint4  br[4];

    // prologue prefetch (chunk 0)
#pragma unroll
    for (int j = 0; j < F4; ++j)
        ar[j] = *reinterpret_cast<const float4*>(aptr + j * 4);
    if (bval) {
#pragma unroll
        for (int j = 0; j < 4; ++j) br[j] = *reinterpret_cast<const uint4*>(bptr + j * 8);
    }

    for (int c = 0; c < NCH; ++c) {
        __syncthreads();    // previous chunk's ldmatrix reads complete
#pragma unroll
        for (int j = 0; j < F4; j += 2) {
            uint32_t u0 = h2b(__floats2half2_rn(ar[j].x,     ar[j].y));
            uint32_t u1 = h2b(__floats2half2_rn(ar[j].z,     ar[j].w));
            uint32_t u2 = h2b(__floats2half2_rn(ar[j + 1].x, ar[j + 1].y));
            uint32_t u3 = h2b(__floats2half2_rn(ar[j + 1].z, ar[j + 1].w));
            STS128(a_st + (uint32_t)(j / 2) * 16u, u0, u1, u2, u3);
        }
        if (bval) {
#pragma unroll
            for (int j = 0; j < 4; ++j)
                STS128(b_st + (uint32_t)j * 16u, br[j].x, br[j].y, br[j].z, br[j].w);
        }
        __syncthreads();
        // prefetch next chunk (LDG latency overlaps MMA below)
        if (c + 1 < NCH) {
#pragma unroll
            for (int j = 0; j < F4; ++j)
                ar[j] = *reinterpret_cast<const float4*>(aptr + (c + 1) * BK + j * 4);
            if (bval) {
#pragma unroll
                for (int j = 0; j < 4; ++j)
                    br[j] = *reinterpret_cast<const uint4*>(bptr + (c + 1) * BK + j * 8);
            }
        }
#pragma unroll
        for (int kk = 0; kk < KST; ++kk) {
            uint32_t a[2][4], b[FN][2];
#pragma unroll
            for (int fm = 0; fm < 2; ++fm)
                LDMATRIX_X4(a[fm][0], a[fm][1], a[fm][2], a[fm][3],
                            a_ld + (uint32_t)fm * 16u * (RS * 2) + (uint32_t)kk * 32u);
#pragma unroll
            for (int fn = 0; fn < FN; ++fn)
                LDMATRIX_X2(b[fn][0], b[fn][1],
                            b_ld + (uint32_t)fn * 8u * (RS * 2) + (uint32_t)kk * 32u);
#pragma unroll
            for (int fm = 0; fm < 2; ++fm)
#pragma unroll
                for (int fn = 0; fn < FN; ++fn)
                    MMA_16816(acc[fm][fn], a[fm], b[fn]);
        }
    }

    // epilogue: bias + silu + topk-weight -> vectorized no-return reduction
    const int qrow = lane >> 2;
    const int qcol = (lane & 3) * 2;
    const float* be = Bias + e * DOUT;
#pragma unroll
    for (int fm = 0; fm < 2; ++fm) {
#pragma unroll
        for (int hf = 0; hf < 2; ++hf) {
            int rloc = warp_m * 32 + fm * 16 + hf * 8 + qrow;
            int m = m0 + rloc;
            if (m >= count) continue;
            float wt = swt[rloc];
            float* orow = Out + (size_t)srow[rloc] * DOUT;
#pragma unroll
            for (int fn = 0; fn < FN; ++fn) {
                int col = warp_n * WN + fn * 8 + qcol;
                float h0 = acc[fm][fn][hf * 2 + 0] + be[col];
                float h1 = acc[fm][fn][hf * 2 + 1] + be[col + 1];
                float s0 = wt * (h0 / (1.f + __expf(-h0)));
                float s1 = wt * (h1 / (1.f + __expf(-h1)));
                RED2_F32(orow + col, s0, s1);
            }
        }
    }
}

// ---------------- launch ----------------------------------------------------
extern "C" void kernel_launch(void* const* d_in, const int* in_sizes, int n_in,
                              void* d_out, int out_size) {
    const float* x_m1 = (const float*)d_in[0];
    const float* x_m2 = (const float*)d_in[1];
    const float* x_e  = (const float*)d_in[2];
    const float* x_a  = (const float*)d_in[3];
    const float* nw   = (const float*)d_in[4];
    const int*   ni   = (const int*)  d_in[5];
    const float* ewn  = (const float*)d_in[6];
    const int*   ein  = (const int*)  d_in[7];
    const float* awn  = (const float*)d_in[8];
    const int*   ain  = (const int*)  d_in[9];
    const int*   n2e  = (const int*)  d_in[10];
    const int*   n2a  = (const int*)  d_in[11];
    const float* W1 = (const float*)d_in[12];
    const float* b1 = (const float*)d_in[13];
    const float* W2 = (const float*)d_in[14];
    const float* b2 = (const float*)d_in[15];
    const float* We = (const float*)d_in[16];
    const float* be = (const float*)d_in[17];
    const float* Wa = (const float*)d_in[18];
    const float* ba = (const float*)d_in[19];
    float* out = (float*)d_out;
    (void)in_sizes; (void)n_in; (void)out_size;

    int n4 = (int)(OUT_TOTAL / 4);

    init_kernel<<<(n4 + 255) / 256, 256>>>(out, n4);
    route_kernel<0><<<N_NODE  / 256, 256>>>(ni,  nw,  nullptr, N_NODE);
    route_kernel<1><<<N_EDGE  / 256, 256>>>(ein, ewn, n2e,     N_EDGE);
    route_kernel<2><<<N_ANGLE / 256, 256>>>(ain, awn, n2a,     N_ANGLE);
    wcvt_kernel<3><<<dim3((ADIM / 32) * (DO_ANGLE / 32), 8), dim3(32, 8)>>>(Wa);
    moe_gemm_mma<3><<<dim3(CAPA / 256, 8), 512>>>(x_a,  ba, out + OUT_ANGLE);
    wcvt_kernel<2><<<dim3((EINFO/ 32) * (DO_EDGE  / 32), 8), dim3(32, 8)>>>(We);
    moe_gemm_mma<2><<<dim3(CAPE / 128, 8), 512>>>(x_e,  be, out + OUT_EDGE);
    wcvt_kernel<1><<<dim3((NSYM / 32) * (DO_NODE  / 32), 8), dim3(32, 8)>>>(W2);
    moe_gemm_mma<1><<<dim3(CAPN / 128, 8), 512>>>(x_m2, b2, out + OUT_M2);
    wcvt_kernel<0><<<dim3((ND   / 32) * (DO_NODE  / 32), 8), dim3(32, 8)>>>(W1);
    moe_gemm_mma<0><<<dim3(CAPN / 128, 8), 512>>>(x_m1, b1, out + OUT_M1);
}